// round 1
// baseline (speedup 1.0000x reference)
#include <cuda_runtime.h>

#define H_ 4
#define N_ 4096
#define D_ 128
#define KX_ 512            // H * D
#define NW_ (N_/32)        // 128 mask words per row
#define NEGV -9e15f
#define ALPHA_ 0.2f
#define BI 64
#define BJ 32

// ---------------- device scratch (no allocations allowed) ----------------
__device__ float    g_Wh[H_*N_*D_];     // 8 MB, reused by both stages
__device__ float    g_x [N_*KX_];       // 8 MB, stage-1 concat output
__device__ unsigned g_adjb[N_*NW_];     // 2 MB adjacency bitmask
__device__ float    g_src [H_*N_];
__device__ float    g_dst [H_*N_];
__device__ float    g_m   [H_*N_];
__device__ float    g_invl[H_*N_];

// ---------------- packed f32x2 helpers (FFMA2 only exists via PTX) -------
__device__ __forceinline__ unsigned long long splat2(float x){
    unsigned long long r;
    asm("mov.b64 %0, {%1, %1};" : "=l"(r) : "f"(x));
    return r;
}
__device__ __forceinline__ void dfma2(unsigned long long& c,
                                      unsigned long long a, unsigned long long b){
    asm("fma.rn.f32x2 %0, %1, %2, %0;" : "+l"(c) : "l"(a), "l"(b));
}
__device__ __forceinline__ float2 unpack2(unsigned long long v){
    float2 f;
    asm("mov.b64 {%0, %1}, %2;" : "=f"(f.x), "=f"(f.y) : "l"(v));
    return f;
}
__device__ __forceinline__ float eluf(float x){ return x > 0.f ? x : expm1f(x); }

// ---------------- K0: pack adj (64MB int32 -> 2MB bits, read once) -------
__global__ void pack_adj(const int* __restrict__ adj) {
    int gwarp  = (blockIdx.x*blockDim.x + threadIdx.x) >> 5;
    int lane   = threadIdx.x & 31;
    int nwarps = (gridDim.x*blockDim.x) >> 5;
    for (int w = gwarp; w < N_*NW_; w += nwarps) {
        int v = adj[(size_t)w*32 + lane];
        unsigned bits = __ballot_sync(0xffffffffu, v > 0);
        if (lane == 0) g_adjb[w] = bits;
    }
}

// ---------------- K1: Wh = X @ W (per head), 128x128 tiles ---------------
__global__ __launch_bounds__(256) void gemm_wh(
    const float* __restrict__ A_ext, int lda, long aHeadStride,
    const float* __restrict__ B, int K, int stage)
{
    __shared__ float As[16][128];
    __shared__ float Bs[16][128];
    int h = blockIdx.z;
    const float* A  = (stage == 2) ? g_x : A_ext;
    const float* Ah = A + (long)h * aHeadStride;
    const float* Bh = B + (long)h * K * D_;
    float*       Ch = g_Wh + (size_t)h * N_ * D_;
    int m0 = blockIdx.x * 128;
    int tid = threadIdx.x;
    int tx = tid & 15, ty = tid >> 4;
    float acc[8][8];
    #pragma unroll
    for (int i=0;i<8;i++)
        #pragma unroll
        for (int j=0;j<8;j++) acc[i][j]=0.f;

    for (int k0 = 0; k0 < K; k0 += 16) {
        #pragma unroll
        for (int l=0;l<2;l++){                 // A tile 128x16 (transposed store)
            int idx = tid + l*256;
            int row = idx >> 2;
            int c4  = idx & 3;
            float4 v = *(const float4*)&Ah[(size_t)(m0+row)*lda + k0 + c4*4];
            As[c4*4+0][row]=v.x; As[c4*4+1][row]=v.y;
            As[c4*4+2][row]=v.z; As[c4*4+3][row]=v.w;
        }
        #pragma unroll
        for (int l=0;l<2;l++){                 // B tile 16x128
            int idx = tid + l*256;
            int row = idx >> 5;
            int c4  = idx & 31;
            *(float4*)&Bs[row][c4*4] = *(const float4*)&Bh[(size_t)(k0+row)*D_ + c4*4];
        }
        __syncthreads();
        #pragma unroll
        for (int k=0;k<16;k++){
            float a[8], b[8];
            *(float4*)(a)   = *(const float4*)&As[k][ty*8];
            *(float4*)(a+4) = *(const float4*)&As[k][ty*8+4];
            *(float4*)(b)   = *(const float4*)&Bs[k][tx*8];
            *(float4*)(b+4) = *(const float4*)&Bs[k][tx*8+4];
            #pragma unroll
            for (int i=0;i<8;i++)
                #pragma unroll
                for (int j=0;j<8;j++)
                    acc[i][j] = fmaf(a[i], b[j], acc[i][j]);
        }
        __syncthreads();
    }
    #pragma unroll
    for (int i=0;i<8;i++){
        size_t row = m0 + ty*8 + i;
        #pragma unroll
        for (int j=0;j<8;j+=4)
            *(float4*)&Ch[row*D_ + tx*8 + j] = *(const float4*)&acc[i][j];
    }
}

// ---------------- K2: src/dst = Wh @ a halves (warp per row) -------------
__global__ void srcdst_k(const float* __restrict__ avec) {
    int h = blockIdx.y;
    int warp = threadIdx.x >> 5, lane = threadIdx.x & 31;
    int i = blockIdx.x*8 + warp;
    const float* wh = g_Wh + ((size_t)h*N_ + i)*D_;
    const float* av = avec + h*2*D_;
    float4 w4 = *(const float4*)&wh[lane*4];
    float4 s4 = *(const float4*)&av[lane*4];
    float4 d4 = *(const float4*)&av[D_ + lane*4];
    float s = w4.x*s4.x + w4.y*s4.y + w4.z*s4.z + w4.w*s4.w;
    float d = w4.x*d4.x + w4.y*d4.y + w4.z*d4.z + w4.w*d4.w;
    #pragma unroll
    for (int o=16;o>0;o>>=1){
        s += __shfl_down_sync(0xffffffffu, s, o);
        d += __shfl_down_sync(0xffffffffu, d, o);
    }
    if (lane==0){ g_src[h*N_+i]=s; g_dst[h*N_+i]=d; }
}

// ---------------- K3: per-row softmax stats (m, 1/l) ---------------------
__global__ __launch_bounds__(128) void rowstats_k() {
    __shared__ float red[128];
    int h = blockIdx.y, i = blockIdx.x, t = threadIdx.x;
    float srci = g_src[h*N_+i];
    const float* dsth = g_dst + h*N_;
    unsigned w = g_adjb[(size_t)i*NW_ + t];          // thread t owns word t
    float dv[32];
    #pragma unroll
    for (int q=0;q<8;q++)
        *(float4*)&dv[q*4] = *(const float4*)&dsth[t*32 + q*4];
    float m = NEGV;
    #pragma unroll
    for (int b=0;b<32;b++){
        if ((w>>b)&1u){
            float s = srci + dv[b];
            float e = s>0.f ? s : ALPHA_*s;
            m = fmaxf(m, e);
        }
    }
    red[t]=m; __syncthreads();
    #pragma unroll
    for (int o=64;o>0;o>>=1){
        if (t<o) red[t] = fmaxf(red[t], red[t+o]);
        __syncthreads();
    }
    m = red[0];
    __syncthreads();
    float l = 0.f;
    #pragma unroll
    for (int b=0;b<32;b++){
        float e = NEGV;                               // masked -> exp underflows to 0;
        if ((w>>b)&1u){                               // all-masked row -> m==NEGV -> exp(0)=1 each (uniform, matches ref)
            float s = srci + dv[b];
            e = s>0.f ? s : ALPHA_*s;
        }
        l += __expf(e - m);
    }
    red[t]=l; __syncthreads();
    #pragma unroll
    for (int o=64;o>0;o>>=1){
        if (t<o) red[t] += red[t+o];
        __syncthreads();
    }
    if (t==0){ g_m[h*N_+i]=m; g_invl[h*N_+i]=1.f/red[0]; }
}

// ---------------- K4: O = elu( P @ Wh ), P computed on the fly -----------
// Block: 64 rows x 128 cols output tile, 256 threads, thread tile 4x8 (FFMA2 pairs).
__global__ __launch_bounds__(256) void attn_k(float* __restrict__ out_ext, int stage) {
    __shared__ float Whs[BJ][128];
    __shared__ float Ps [BJ][BI];
    __shared__ float srcS[BI], mS[BI], ilS[BI];
    int h  = blockIdx.y;
    int i0 = blockIdx.x * BI;
    int tid = threadIdx.x;
    float* outp = (stage==1) ? g_x : out_ext;
    const float* Wh = g_Wh + (size_t)h*N_*D_;
    if (tid < BI) {
        srcS[tid] = g_src [h*N_ + i0 + tid];
        mS[tid]   = g_m   [h*N_ + i0 + tid];
        ilS[tid]  = g_invl[h*N_ + i0 + tid];
    }
    int tx = tid & 15, ty = tid >> 4;       // compute layout
    int r  = tid & 63, jg = tid >> 6;       // P-compute layout
    unsigned long long acc2[4][4];
    #pragma unroll
    for (int i=0;i<4;i++)
        #pragma unroll
        for (int j=0;j<4;j++) acc2[i][j]=0ull;
    __syncthreads();

    for (int j0 = 0; j0 < N_; j0 += BJ) {
        #pragma unroll
        for (int l=0;l<4;l++){               // Wh tile 32x128
            int idx = tid + l*256;
            int row = idx >> 5;
            int c4  = idx & 31;
            *(float4*)&Whs[row][c4*4] = *(const float4*)&Wh[(size_t)(j0+row)*D_ + c4*4];
        }
        {   // P tile 32(j) x 64(i): thread -> row r, cols jg*8..jg*8+7
            unsigned w = g_adjb[(size_t)(i0+r)*NW_ + (j0>>5)];
            float sr = srcS[r], mi = mS[r], il = ilS[r];
            const float* dsth = g_dst + h*N_ + j0 + jg*8;
            #pragma unroll
            for (int q=0;q<8;q++){
                int jj = jg*8 + q;
                float e = NEGV;
                if ((w>>jj)&1u){
                    float s = sr + dsth[q];
                    e = s>0.f ? s : ALPHA_*s;
                }
                Ps[jj][r] = __expf(e - mi) * il;
            }
        }
        __syncthreads();
        #pragma unroll 8
        for (int k=0;k<BJ;k++){
            float4 av = *(const float4*)&Ps[k][ty*4];
            const unsigned long long* bp = (const unsigned long long*)&Whs[k][tx*8];
            unsigned long long b0=bp[0], b1=bp[1], b2=bp[2], b3=bp[3];
            unsigned long long a0=splat2(av.x), a1=splat2(av.y),
                               a2=splat2(av.z), a3=splat2(av.w);
            dfma2(acc2[0][0],a0,b0); dfma2(acc2[0][1],a0,b1); dfma2(acc2[0][2],a0,b2); dfma2(acc2[0][3],a0,b3);
            dfma2(acc2[1][0],a1,b0); dfma2(acc2[1][1],a1,b1); dfma2(acc2[1][2],a1,b2); dfma2(acc2[1][3],a1,b3);
            dfma2(acc2[2][0],a2,b0); dfma2(acc2[2][1],a2,b1); dfma2(acc2[2][2],a2,b2); dfma2(acc2[2][3],a2,b3);
            dfma2(acc2[3][0],a3,b0); dfma2(acc2[3][1],a3,b1); dfma2(acc2[3][2],a3,b2); dfma2(acc2[3][3],a3,b3);
        }
        __syncthreads();
    }
    #pragma unroll
    for (int ii=0;ii<4;ii++){
        size_t row = i0 + ty*4 + ii;
        float v[8];
        #pragma unroll
        for (int jp=0;jp<4;jp++){
            float2 f = unpack2(acc2[ii][jp]);
            v[jp*2]   = eluf(f.x);
            v[jp*2+1] = eluf(f.y);
        }
        float* orow = outp + row*KX_ + h*D_ + tx*8;
        *(float4*)(orow)   = *(const float4*)&v[0];
        *(float4*)(orow+4) = *(const float4*)&v[4];
    }
}

// ---------------- launch --------------------------------------------------
extern "C" void kernel_launch(void* const* d_in, const int* in_sizes, int n_in,
                              void* d_out, int out_size) {
    const float* chems = (const float*)d_in[0];
    const int*   adj   = (const int*)  d_in[1];
    const float* W1    = (const float*)d_in[2];
    const float* a1    = (const float*)d_in[3];
    const float* W2    = (const float*)d_in[4];
    const float* a2    = (const float*)d_in[5];
    float* out = (float*)d_out;

    pack_adj<<<1024, 256>>>(adj);

    // stage 1: per-head input chems[h], W1[h]
    gemm_wh<<<dim3(N_/128,1,H_), 256>>>(chems, D_, (long)N_*D_, W1, D_, 1);
    srcdst_k<<<dim3(N_/8, H_), 256>>>(a1);
    rowstats_k<<<dim3(N_, H_), 128>>>();
    attn_k<<<dim3(N_/BI, H_), 256>>>(nullptr, 1);   // writes g_x[:, h*128..]

    // stage 2: shared input g_x, W2[h]
    gemm_wh<<<dim3(N_/128,1,H_), 256>>>(nullptr, KX_, 0, W2, KX_, 2);
    srcdst_k<<<dim3(N_/8, H_), 256>>>(a2);
    rowstats_k<<<dim3(N_, H_), 128>>>();
    attn_k<<<dim3(N_/BI, H_), 256>>>(out, 2);       // writes out[:, h*128..]
}

// round 3
// speedup vs baseline: 2.7375x; 2.7375x over previous
#include <cuda_runtime.h>
#include <cuda_bf16.h>
#include <cstdint>

#define H_ 4
#define N_ 4096
#define D_ 128
#define KX_ 512            // H * D
#define NW_ (N_/32)        // 128 mask words per row
#define ALPHA_ 0.2f

// ---------------- device scratch ----------------
__device__ float          g_Wh[H_*N_*D_];        // 8 MB fp32 Wh
__device__ float          g_x [N_*KX_];          // 8 MB stage-1 output
__device__ unsigned       g_adjb[N_*NW_];        // 2 MB adjacency bitmask
__device__ float          g_src [H_*N_];
__device__ float          g_dst [H_*N_];
__device__ __nv_bfloat16  g_whT_hi[H_*D_*N_];    // 4 MB Wh^T hi [h][f][j]
__device__ __nv_bfloat16  g_whT_lo[H_*D_*N_];    // 4 MB Wh^T lo

// ---------------- helpers ----------------
__device__ __forceinline__ uint32_t smem_u32(const void* p){
    uint32_t a;
    asm("{ .reg .u64 t; cvta.to.shared.u64 t, %1; cvt.u32.u64 %0, t; }"
        : "=r"(a) : "l"(p));
    return a;
}
#define SW128(o) ((o) ^ (((o) >> 3) & 0x70))

__device__ __forceinline__ unsigned long long splat2(float x){
    unsigned long long r;
    asm("mov.b64 %0, {%1, %1};" : "=l"(r) : "f"(x));
    return r;
}
__device__ __forceinline__ void dfma2(unsigned long long& c,
                                      unsigned long long a, unsigned long long b){
    asm("fma.rn.f32x2 %0, %1, %2, %0;" : "+l"(c) : "l"(a), "l"(b));
}
__device__ __forceinline__ float2 unpack2(unsigned long long v){
    float2 f;
    asm("mov.b64 {%0, %1}, %2;" : "=f"(f.x), "=f"(f.y) : "l"(v));
    return f;
}
__device__ __forceinline__ float eluf(float x){ return x > 0.f ? x : expm1f(x); }

// fast exp: MUFU-free (fma/alu pipes). |rel err| ~ 2.4e-6 for bounded inputs.
__device__ __forceinline__ float fexp(float x){
    const float L2E   = 1.4426950408889634f;
    const float MAGIC = 12582912.0f;          // 1.5 * 2^23
    float t  = x * L2E;
    float kf = t + MAGIC;
    int   ki = __float_as_int(kf);
    float km = kf - MAGIC;
    float f  = t - km;                        // f in [-0.5, 0.5]
    float p  = 1.33335581e-3f;
    p = fmaf(p, f, 9.61812910e-3f);
    p = fmaf(p, f, 5.55041087e-2f);
    p = fmaf(p, f, 2.40226507e-1f);
    p = fmaf(p, f, 6.93147180e-1f);
    p = fmaf(p, f, 1.0f);
    return __int_as_float(__float_as_int(p) + (int)((unsigned)ki << 23));
}

// ldmatrix / mma.sync (base-target instructions, OK for .target sm_103)
__device__ __forceinline__ void ldsm4(uint32_t* r, uint32_t addr){
    asm volatile("ldmatrix.sync.aligned.m8n8.x4.shared.b16 {%0,%1,%2,%3}, [%4];"
        : "=r"(r[0]),"=r"(r[1]),"=r"(r[2]),"=r"(r[3]) : "r"(addr));
}
__device__ __forceinline__ void mma16816(float* c, const uint32_t* a, const uint32_t* b){
    asm volatile("mma.sync.aligned.m16n8k16.row.col.f32.bf16.bf16.f32 "
        "{%0,%1,%2,%3}, {%4,%5,%6,%7}, {%8,%9}, {%0,%1,%2,%3};"
        : "+f"(c[0]),"+f"(c[1]),"+f"(c[2]),"+f"(c[3])
        : "r"(a[0]),"r"(a[1]),"r"(a[2]),"r"(a[3]), "r"(b[0]),"r"(b[1]));
}

// ---------------- K0: pack adj ----------------
__global__ void pack_adj(const int* __restrict__ adj) {
    int gwarp  = (blockIdx.x*blockDim.x + threadIdx.x) >> 5;
    int lane   = threadIdx.x & 31;
    int nwarps = (gridDim.x*blockDim.x) >> 5;
    for (int w = gwarp; w < N_*NW_; w += nwarps) {
        int v = adj[(size_t)w*32 + lane];
        unsigned bits = __ballot_sync(0xffffffffu, v > 0);
        if (lane == 0) g_adjb[w] = bits;
    }
}

// ---------------- K1: Wh = X @ W (FFMA2 inner loop) ----------------
__global__ __launch_bounds__(256) void gemm_wh(
    const float* __restrict__ A_ext, int lda, long aHeadStride,
    const float* __restrict__ B, int K, int stage)
{
    __shared__ float As[16][128];
    __shared__ float Bs[16][128];
    int h = blockIdx.z;
    const float* A  = (stage == 2) ? g_x : A_ext;
    const float* Ah = A + (long)h * aHeadStride;
    const float* Bh = B + (long)h * K * D_;
    float*       Ch = g_Wh + (size_t)h * N_ * D_;
    int m0 = blockIdx.x * 128;
    int tid = threadIdx.x;
    int tx = tid & 15, ty = tid >> 4;
    unsigned long long acc2[8][4];
    #pragma unroll
    for (int i=0;i<8;i++)
        #pragma unroll
        for (int j=0;j<4;j++) acc2[i][j]=0ull;

    for (int k0 = 0; k0 < K; k0 += 16) {
        #pragma unroll
        for (int l=0;l<2;l++){
            int idx = tid + l*256;
            int row = idx >> 2;
            int c4  = idx & 3;
            float4 v = *(const float4*)&Ah[(size_t)(m0+row)*lda + k0 + c4*4];
            As[c4*4+0][row]=v.x; As[c4*4+1][row]=v.y;
            As[c4*4+2][row]=v.z; As[c4*4+3][row]=v.w;
        }
        #pragma unroll
        for (int l=0;l<2;l++){
            int idx = tid + l*256;
            int row = idx >> 5;
            int c4  = idx & 31;
            *(float4*)&Bs[row][c4*4] = *(const float4*)&Bh[(size_t)(k0+row)*D_ + c4*4];
        }
        __syncthreads();
        #pragma unroll
        for (int k=0;k<16;k++){
            float a[8];
            *(float4*)(a)   = *(const float4*)&As[k][ty*8];
            *(float4*)(a+4) = *(const float4*)&As[k][ty*8+4];
            const unsigned long long* bpr = (const unsigned long long*)&Bs[k][tx*8];
            unsigned long long b0=bpr[0], b1=bpr[1], b2=bpr[2], b3=bpr[3];
            #pragma unroll
            for (int i=0;i<8;i++){
                unsigned long long as = splat2(a[i]);
                dfma2(acc2[i][0],as,b0); dfma2(acc2[i][1],as,b1);
                dfma2(acc2[i][2],as,b2); dfma2(acc2[i][3],as,b3);
            }
        }
        __syncthreads();
    }
    #pragma unroll
    for (int i=0;i<8;i++){
        size_t row = m0 + ty*8 + i;
        float v[8];
        #pragma unroll
        for (int jp=0;jp<4;jp++){
            float2 f = unpack2(acc2[i][jp]);
            v[jp*2] = f.x; v[jp*2+1] = f.y;
        }
        *(float4*)&Ch[row*D_ + tx*8    ] = *(const float4*)&v[0];
        *(float4*)&Ch[row*D_ + tx*8 + 4] = *(const float4*)&v[4];
    }
}

// ---------------- K1b: Wh^T -> bf16 hi/lo ----------------
__global__ __launch_bounds__(256) void cvt_whT() {
    __shared__ float ts[32][33];
    int h  = blockIdx.z;
    int j0 = blockIdx.x * 32;
    int f0 = blockIdx.y * 32;
    int tx = threadIdx.x & 31, ty = threadIdx.x >> 5;
    const float* Wh = g_Wh + (size_t)h*N_*D_;
    #pragma unroll
    for (int r=0;r<4;r++){
        int j = j0 + ty + r*8;
        ts[ty + r*8][tx] = Wh[(size_t)j*D_ + f0 + tx];
    }
    __syncthreads();
    #pragma unroll
    for (int r=0;r<4;r++){
        int f = f0 + ty + r*8;
        float v = ts[tx][ty + r*8];
        __nv_bfloat16 hi = __float2bfloat16(v);
        __nv_bfloat16 lo = __float2bfloat16(v - __bfloat162float(hi));
        size_t o = ((size_t)(h*D_ + f))*N_ + j0 + tx;
        g_whT_hi[o] = hi;
        g_whT_lo[o] = lo;
    }
}

// ---------------- K2: src/dst ----------------
__global__ void srcdst_k(const float* __restrict__ avec) {
    int h = blockIdx.y;
    int warp = threadIdx.x >> 5, lane = threadIdx.x & 31;
    int i = blockIdx.x*8 + warp;
    const float* wh = g_Wh + ((size_t)h*N_ + i)*D_;
    const float* av = avec + h*2*D_;
    float4 w4 = *(const float4*)&wh[lane*4];
    float4 s4 = *(const float4*)&av[lane*4];
    float4 d4 = *(const float4*)&av[D_ + lane*4];
    float s = w4.x*s4.x + w4.y*s4.y + w4.z*s4.z + w4.w*s4.w;
    float d = w4.x*d4.x + w4.y*d4.y + w4.z*d4.z + w4.w*d4.w;
    #pragma unroll
    for (int o=16;o>0;o>>=1){
        s += __shfl_down_sync(0xffffffffu, s, o);
        d += __shfl_down_sync(0xffffffffu, d, o);
    }
    if (lane==0){ g_src[h*N_+i]=s; g_dst[h*N_+i]=d; }
}

// ---------------- K3: O = elu( softmax(P) @ Wh ), HMMA bf16x3 -----------
// CTA: 128x128 output tile, 256 thr (8 warps, 2x4). K-chunk = 64.
// Unnormalized exp accumulated; row-sum folded in; normalize in epilogue.
#define PB_HI 0
#define PB_LO 16384
#define WB_HI 32768
#define WB_LO 49152
#define OFF_L 65536
#define SMEM_DYN (65536 + 512 + 1024)

__global__ __launch_bounds__(256,1) void attn_hmma(float* __restrict__ out_ext, int stage) {
    extern __shared__ char dsm[];
    uint32_t raw = smem_u32(dsm);
    uint32_t sb  = (raw + 1023) & ~1023u;
    char* bp = dsm + (sb - raw);
    float* sml = (float*)(bp + OFF_L);

    int h = blockIdx.y, i0 = blockIdx.x*128;
    int tid = threadIdx.x, lane = tid & 31, wid = tid >> 5;
    float* outp = (stage==1) ? g_x : out_ext;
    int r = tid >> 1, jh = tid & 1;
    float srcr = g_src[h*N_ + i0 + r];
    const float* dsth = g_dst + h*N_;
    const char* whh = (const char*)(g_whT_hi + (size_t)h*D_*N_);
    const char* whl = (const char*)(g_whT_lo + (size_t)h*D_*N_);
    int wm = wid >> 2, wn = wid & 3;
    float rsum = 0.f;
    float acc[4][4][4];
    #pragma unroll
    for (int a=0;a<4;a++)
        #pragma unroll
        for (int b=0;b<4;b++)
            #pragma unroll
            for (int c=0;c<4;c++) acc[a][b][c]=0.f;

    for (int c = 0; c < 64; ++c) {
        int j0 = c * 64;
        // -- Wh^T tiles (hi/lo), [128 f][64 j] bf16, swizzled --
        #pragma unroll
        for (int l=0;l<4;l++){
            int idx = tid + l*256;
            int f = idx >> 3, seg = idx & 7;
            size_t go = (((size_t)f*N_ + j0) << 1) + (size_t)seg*16;
            uint32_t so = SW128((uint32_t)(f*128 + seg*16));
            *(float4*)(bp + WB_HI + so) = *(const float4*)(whh + go);
            *(float4*)(bp + WB_LO + so) = *(const float4*)(whl + go);
        }
        // -- P tile: row r, 32 j (half jh); unnormalized exp, bf16 hi/lo --
        {
            unsigned w = g_adjb[(size_t)(i0+r)*NW_ + (j0>>5) + jh];
            float dv[32];
            const float* dp = dsth + j0 + jh*32;
            #pragma unroll
            for (int q=0;q<8;q++) *(float4*)&dv[q*4] = *(const float4*)(dp + q*4);
            uint32_t rb = (uint32_t)(r*128 + jh*64);
            #pragma unroll
            for (int q=0;q<16;q++){
                float s0 = srcr + dv[2*q];
                float s1 = srcr + dv[2*q+1];
                s0 = fmaxf(s0, ALPHA_*s0);
                s1 = fmaxf(s1, ALPHA_*s1);
                float p0 = fexp(s0), p1 = fexp(s1);
                p0 = ((w>>(2*q  ))&1u) ? p0 : 0.f;
                p1 = ((w>>(2*q+1))&1u) ? p1 : 0.f;
                rsum += p0 + p1;
                __nv_bfloat162 hp = __floats2bfloat162_rn(p0, p1);
                uint32_t hb = *(uint32_t*)&hp;
                float h0 = __uint_as_float(hb << 16);
                float h1 = __uint_as_float(hb & 0xffff0000u);
                __nv_bfloat162 lp = __floats2bfloat162_rn(p0 - h0, p1 - h1);
                uint32_t so = SW128(rb + q*4);
                *(uint32_t*)(bp + PB_HI + so) = hb;
                *(uint32_t*)(bp + PB_LO + so) = *(uint32_t*)&lp;
            }
        }
        __syncthreads();
        // -- MMA: warp tile 64(M) x 32(N), 3 bf16 terms --
        #pragma unroll
        for (int kt=0;kt<4;kt++){
            uint32_t ah[4][4], al[4][4], bh[4][2], bl[4][2];
            uint32_t kb = (uint32_t)(kt*32 + (lane>>4)*16);
            #pragma unroll
            for (int mt=0;mt<4;mt++){
                uint32_t off = SW128((uint32_t)((wm*64 + mt*16 + (lane&15))*128) + kb);
                ldsm4(ah[mt], sb + PB_HI + off);
                ldsm4(al[mt], sb + PB_LO + off);
            }
            #pragma unroll
            for (int pp=0;pp<2;pp++){
                uint32_t off = SW128((uint32_t)((wn*32 + pp*16 + (lane&15))*128) + kb);
                uint32_t t0[4], t1[4];
                ldsm4(t0, sb + WB_HI + off);
                ldsm4(t1, sb + WB_LO + off);
                bh[pp*2  ][0]=t0[0]; bh[pp*2  ][1]=t0[2];
                bh[pp*2+1][0]=t0[1]; bh[pp*2+1][1]=t0[3];
                bl[pp*2  ][0]=t1[0]; bl[pp*2  ][1]=t1[2];
                bl[pp*2+1][0]=t1[1]; bl[pp*2+1][1]=t1[3];
            }
            #pragma unroll
            for (int mt=0;mt<4;mt++)
                #pragma unroll
                for (int nt=0;nt<4;nt++){
                    mma16816(acc[mt][nt], ah[mt], bh[nt]);
                    mma16816(acc[mt][nt], ah[mt], bl[nt]);
                    mma16816(acc[mt][nt], al[mt], bh[nt]);
                }
        }
        __syncthreads();
    }
    // -- row sums -> 1/l in smem --
    float full = rsum + __shfl_xor_sync(0xffffffffu, rsum, 1);
    if (!(tid & 1)) sml[r] = 1.0f / full;
    __syncthreads();
    // -- epilogue: normalize, elu, store --
    #pragma unroll
    for (int mt=0;mt<4;mt++){
        int r0 = wm*64 + mt*16 + (lane>>2);
        float il0 = sml[r0], il1 = sml[r0+8];
        #pragma unroll
        for (int nt=0;nt<4;nt++){
            int fcol = wn*32 + nt*8 + (lane&3)*2;
            float2 v0, v1;
            v0.x = eluf(acc[mt][nt][0]*il0);
            v0.y = eluf(acc[mt][nt][1]*il0);
            v1.x = eluf(acc[mt][nt][2]*il1);
            v1.y = eluf(acc[mt][nt][3]*il1);
            *(float2*)(outp + (size_t)(i0+r0  )*KX_ + h*D_ + fcol) = v0;
            *(float2*)(outp + (size_t)(i0+r0+8)*KX_ + h*D_ + fcol) = v1;
        }
    }
}

// ---------------- launch ----------------
extern "C" void kernel_launch(void* const* d_in, const int* in_sizes, int n_in,
                              void* d_out, int out_size) {
    const float* chems = (const float*)d_in[0];
    const int*   adj   = (const int*)  d_in[1];
    const float* W1    = (const float*)d_in[2];
    const float* a1    = (const float*)d_in[3];
    const float* W2    = (const float*)d_in[4];
    const float* a2    = (const float*)d_in[5];
    float* out = (float*)d_out;

    cudaFuncSetAttribute(attn_hmma, cudaFuncAttributeMaxDynamicSharedMemorySize, SMEM_DYN);

    pack_adj<<<1024, 256>>>(adj);

    // stage 1
    gemm_wh<<<dim3(N_/128,1,H_), 256>>>(chems, D_, (long)N_*D_, W1, D_, 1);
    cvt_whT<<<dim3(N_/32, D_/32, H_), 256>>>();
    srcdst_k<<<dim3(N_/8, H_), 256>>>(a1);
    attn_hmma<<<dim3(N_/128, H_), 256, SMEM_DYN>>>(nullptr, 1);

    // stage 2
    gemm_wh<<<dim3(N_/128,1,H_), 256>>>(nullptr, KX_, 0, W2, KX_, 2);
    cvt_whT<<<dim3(N_/32, D_/32, H_), 256>>>();
    srcdst_k<<<dim3(N_/8, H_), 256>>>(a2);
    attn_hmma<<<dim3(N_/128, H_), 256, SMEM_DYN>>>(out, 2);
}

// round 4
// speedup vs baseline: 2.8333x; 1.0350x over previous
#include <cuda_runtime.h>
#include <cuda_bf16.h>
#include <cstdint>

#define H_ 4
#define N_ 4096
#define D_ 128
#define KX_ 512            // H * D
#define NW_ (N_/32)        // 128 mask words per row
#define ALPHA_ 0.2f

// ---------------- device scratch ----------------
__device__ float          g_Wh[H_*N_*D_];        // 8 MB fp32 Wh
__device__ float          g_x [N_*KX_];          // 8 MB stage-1 output
__device__ unsigned       g_adjb[N_*NW_];        // 2 MB adjacency bitmask
__device__ float2         g_EFs[H_*N_];          // rows: {e^s, e^.2s}
__device__ float2         g_EFd[H_*N_];          // cols: {e^d, e^.2d}
__device__ __nv_bfloat16  g_whT_hi[H_*D_*N_];    // 4 MB Wh^T hi [h][f][j]
__device__ __nv_bfloat16  g_whT_lo[H_*D_*N_];    // 4 MB Wh^T lo

// ---------------- helpers ----------------
__device__ __forceinline__ uint32_t smem_u32(const void* p){
    uint32_t a;
    asm("{ .reg .u64 t; cvta.to.shared.u64 t, %1; cvt.u32.u64 %0, t; }"
        : "=r"(a) : "l"(p));
    return a;
}
#define SW128(o) ((o) ^ (((o) >> 3) & 0x70))

__device__ __forceinline__ unsigned long long splat2(float x){
    unsigned long long r;
    asm("mov.b64 %0, {%1, %1};" : "=l"(r) : "f"(x));
    return r;
}
__device__ __forceinline__ void dfma2(unsigned long long& c,
                                      unsigned long long a, unsigned long long b){
    asm("fma.rn.f32x2 %0, %1, %2, %0;" : "+l"(c) : "l"(a), "l"(b));
}
__device__ __forceinline__ float2 unpack2(unsigned long long v){
    float2 f;
    asm("mov.b64 {%0, %1}, %2;" : "=f"(f.x), "=f"(f.y) : "l"(v));
    return f;
}
__device__ __forceinline__ float eluf(float x){ return x > 0.f ? x : expm1f(x); }

// fast exp on fma/alu pipes (used only for per-node precompute now)
__device__ __forceinline__ float fexp(float x){
    const float L2E   = 1.4426950408889634f;
    const float MAGIC = 12582912.0f;
    float t  = x * L2E;
    float kf = t + MAGIC;
    int   ki = __float_as_int(kf);
    float km = kf - MAGIC;
    float f  = t - km;
    float p  = 1.33335581e-3f;
    p = fmaf(p, f, 9.61812910e-3f);
    p = fmaf(p, f, 5.55041087e-2f);
    p = fmaf(p, f, 2.40226507e-1f);
    p = fmaf(p, f, 6.93147180e-1f);
    p = fmaf(p, f, 1.0f);
    return __int_as_float(__float_as_int(p) + (int)((unsigned)ki << 23));
}

__device__ __forceinline__ void ldsm4(uint32_t* r, uint32_t addr){
    asm volatile("ldmatrix.sync.aligned.m8n8.x4.shared.b16 {%0,%1,%2,%3}, [%4];"
        : "=r"(r[0]),"=r"(r[1]),"=r"(r[2]),"=r"(r[3]) : "r"(addr));
}
__device__ __forceinline__ void mma16816(float* c, const uint32_t* a, const uint32_t* b){
    asm volatile("mma.sync.aligned.m16n8k16.row.col.f32.bf16.bf16.f32 "
        "{%0,%1,%2,%3}, {%4,%5,%6,%7}, {%8,%9}, {%0,%1,%2,%3};"
        : "+f"(c[0]),"+f"(c[1]),"+f"(c[2]),"+f"(c[3])
        : "r"(a[0]),"r"(a[1]),"r"(a[2]),"r"(a[3]), "r"(b[0]),"r"(b[1]));
}
__device__ __forceinline__ void cpasync16(uint32_t dst, const void* src){
    asm volatile("cp.async.cg.shared.global [%0], [%1], 16;" :: "r"(dst), "l"(src));
}
#define CP_COMMIT() asm volatile("cp.async.commit_group;" ::: "memory")
#define CP_WAIT0()  asm volatile("cp.async.wait_group 0;"  ::: "memory")

// ---------------- K0: pack adj ----------------
__global__ void pack_adj(const int* __restrict__ adj) {
    int gwarp  = (blockIdx.x*blockDim.x + threadIdx.x) >> 5;
    int lane   = threadIdx.x & 31;
    int nwarps = (gridDim.x*blockDim.x) >> 5;
    for (int w = gwarp; w < N_*NW_; w += nwarps) {
        int v = adj[(size_t)w*32 + lane];
        unsigned bits = __ballot_sync(0xffffffffu, v > 0);
        if (lane == 0) g_adjb[w] = bits;
    }
}

// ---------------- K1: Wh = X @ W (FFMA2) ----------------
__global__ __launch_bounds__(256) void gemm_wh(
    const float* __restrict__ A_ext, int lda, long aHeadStride,
    const float* __restrict__ B, int K, int stage)
{
    __shared__ float As[16][128];
    __shared__ float Bs[16][128];
    int h = blockIdx.z;
    const float* A  = (stage == 2) ? g_x : A_ext;
    const float* Ah = A + (long)h * aHeadStride;
    const float* Bh = B + (long)h * K * D_;
    float*       Ch = g_Wh + (size_t)h * N_ * D_;
    int m0 = blockIdx.x * 128;
    int tid = threadIdx.x;
    int tx = tid & 15, ty = tid >> 4;
    unsigned long long acc2[8][4];
    #pragma unroll
    for (int i=0;i<8;i++)
        #pragma unroll
        for (int j=0;j<4;j++) acc2[i][j]=0ull;

    for (int k0 = 0; k0 < K; k0 += 16) {
        #pragma unroll
        for (int l=0;l<2;l++){
            int idx = tid + l*256;
            int row = idx >> 2;
            int c4  = idx & 3;
            float4 v = *(const float4*)&Ah[(size_t)(m0+row)*lda + k0 + c4*4];
            As[c4*4+0][row]=v.x; As[c4*4+1][row]=v.y;
            As[c4*4+2][row]=v.z; As[c4*4+3][row]=v.w;
        }
        #pragma unroll
        for (int l=0;l<2;l++){
            int idx = tid + l*256;
            int row = idx >> 5;
            int c4  = idx & 31;
            *(float4*)&Bs[row][c4*4] = *(const float4*)&Bh[(size_t)(k0+row)*D_ + c4*4];
        }
        __syncthreads();
        #pragma unroll
        for (int k=0;k<16;k++){
            float a[8];
            *(float4*)(a)   = *(const float4*)&As[k][ty*8];
            *(float4*)(a+4) = *(const float4*)&As[k][ty*8+4];
            const unsigned long long* bpr = (const unsigned long long*)&Bs[k][tx*8];
            unsigned long long b0=bpr[0], b1=bpr[1], b2=bpr[2], b3=bpr[3];
            #pragma unroll
            for (int i=0;i<8;i++){
                unsigned long long as = splat2(a[i]);
                dfma2(acc2[i][0],as,b0); dfma2(acc2[i][1],as,b1);
                dfma2(acc2[i][2],as,b2); dfma2(acc2[i][3],as,b3);
            }
        }
        __syncthreads();
    }
    #pragma unroll
    for (int i=0;i<8;i++){
        size_t row = m0 + ty*8 + i;
        float v[8];
        #pragma unroll
        for (int jp=0;jp<4;jp++){
            float2 f = unpack2(acc2[i][jp]);
            v[jp*2] = f.x; v[jp*2+1] = f.y;
        }
        *(float4*)&Ch[row*D_ + tx*8    ] = *(const float4*)&v[0];
        *(float4*)&Ch[row*D_ + tx*8 + 4] = *(const float4*)&v[4];
    }
}

// ---------------- K1b: Wh^T -> bf16 hi/lo ----------------
__global__ __launch_bounds__(256) void cvt_whT() {
    __shared__ float ts[32][33];
    int h  = blockIdx.z;
    int j0 = blockIdx.x * 32;
    int f0 = blockIdx.y * 32;
    int tx = threadIdx.x & 31, ty = threadIdx.x >> 5;
    const float* Wh = g_Wh + (size_t)h*N_*D_;
    #pragma unroll
    for (int r=0;r<4;r++){
        int j = j0 + ty + r*8;
        ts[ty + r*8][tx] = Wh[(size_t)j*D_ + f0 + tx];
    }
    __syncthreads();
    #pragma unroll
    for (int r=0;r<4;r++){
        int f = f0 + ty + r*8;
        float v = ts[tx][ty + r*8];
        __nv_bfloat16 hi = __float2bfloat16(v);
        __nv_bfloat16 lo = __float2bfloat16(v - __bfloat162float(hi));
        size_t o = ((size_t)(h*D_ + f))*N_ + j0 + tx;
        g_whT_hi[o] = hi;
        g_whT_lo[o] = lo;
    }
}

// ---------------- K2: src/dst dots -> per-node exp factors ---------------
__global__ void srcdst_k(const float* __restrict__ avec) {
    int h = blockIdx.y;
    int warp = threadIdx.x >> 5, lane = threadIdx.x & 31;
    int i = blockIdx.x*8 + warp;
    const float* wh = g_Wh + ((size_t)h*N_ + i)*D_;
    const float* av = avec + h*2*D_;
    float4 w4 = *(const float4*)&wh[lane*4];
    float4 s4 = *(const float4*)&av[lane*4];
    float4 d4 = *(const float4*)&av[D_ + lane*4];
    float s = w4.x*s4.x + w4.y*s4.y + w4.z*s4.z + w4.w*s4.w;
    float d = w4.x*d4.x + w4.y*d4.y + w4.z*d4.z + w4.w*d4.w;
    #pragma unroll
    for (int o=16;o>0;o>>=1){
        s += __shfl_down_sync(0xffffffffu, s, o);
        d += __shfl_down_sync(0xffffffffu, d, o);
    }
    if (lane==0){
        g_EFs[h*N_+i] = make_float2(fexp(s), fexp(ALPHA_*s));
        g_EFd[h*N_+i] = make_float2(fexp(d), fexp(ALPHA_*d));
    }
}

// ---------------- K3: O = elu( softmax(P) @ Wh ), pipelined HMMA ---------
// p_ij = max(E_i*E_j, F_i*F_j)  ==  exp(leaky_relu(s_i + d_j))
#define PB_HI 0
#define PB_LO 16384
#define WB_HI 32768
#define WB_LO 49152
#define BUFSZ 65536
#define OFF_L (2*BUFSZ)
#define SMEM_DYN (2*BUFSZ + 512 + 1024)

__global__ __launch_bounds__(256,1) void attn_hmma(float* __restrict__ out_ext, int stage) {
    extern __shared__ char dsm[];
    uint32_t raw = smem_u32(dsm);
    uint32_t sb  = (raw + 1023) & ~1023u;
    char* bp = dsm + (sb - raw);
    float* sml = (float*)(bp + OFF_L);

    int h = blockIdx.y, i0 = blockIdx.x*128;
    int tid = threadIdx.x, lane = tid & 31, wid = tid >> 5;
    float* outp = (stage==1) ? g_x : out_ext;
    int r = tid >> 1, jh = tid & 1;
    float2 efs = g_EFs[h*N_ + i0 + r];
    float Ei = efs.x, Fi = efs.y;
    const float2*  efd    = g_EFd + h*N_;
    const unsigned* adjrow = g_adjb + (size_t)(i0+r)*NW_;
    const char* whh = (const char*)(g_whT_hi + (size_t)h*D_*N_);
    const char* whl = (const char*)(g_whT_lo + (size_t)h*D_*N_);
    int wm = wid >> 2, wn = wid & 3;
    float rsum = 0.f;
    float acc[4][4][4];
    #pragma unroll
    for (int a=0;a<4;a++)
        #pragma unroll
        for (int b=0;b<4;b++)
            #pragma unroll
            for (int c=0;c<4;c++) acc[a][b][c]=0.f;

    // W-tile async load into buffer tb for chunk c
    auto loadW = [&](uint32_t tb, int c){
        int j0 = c * 64;
        #pragma unroll
        for (int l=0;l<4;l++){
            int idx = tid + l*256;
            int f = idx >> 3, seg = idx & 7;
            size_t go = (((size_t)f*N_ + j0) << 1) + (size_t)seg*16;
            uint32_t so = SW128((uint32_t)(f*128 + seg*16));
            cpasync16(sb + tb + WB_HI + so, whh + go);
            cpasync16(sb + tb + WB_LO + so, whl + go);
        }
        CP_COMMIT();
    };
    // P-tile generation into buffer tb for chunk c (this thread: row r, half jh)
    auto genP = [&](uint32_t tb, int c){
        int j0 = c * 64;
        unsigned w = adjrow[(j0>>5) + jh];
        const float4* efp = (const float4*)(efd + j0 + jh*32);
        uint32_t rb = (uint32_t)(r*128 + jh*64);
        #pragma unroll
        for (int q=0;q<16;q++){
            float4 e01 = efp[q];                 // {E_j0,F_j0,E_j1,F_j1}
            float p0 = fmaxf(Ei*e01.x, Fi*e01.y);
            float p1 = fmaxf(Ei*e01.z, Fi*e01.w);
            p0 = ((w>>(2*q  ))&1u) ? p0 : 0.f;
            p1 = ((w>>(2*q+1))&1u) ? p1 : 0.f;
            rsum += p0 + p1;
            __nv_bfloat162 hp = __floats2bfloat162_rn(p0, p1);
            uint32_t hb = *(uint32_t*)&hp;
            float h0 = __uint_as_float(hb << 16);
            float h1 = __uint_as_float(hb & 0xffff0000u);
            __nv_bfloat162 lp = __floats2bfloat162_rn(p0 - h0, p1 - h1);
            uint32_t so = SW128(rb + q*4);
            *(uint32_t*)(bp + tb + PB_HI + so) = hb;
            *(uint32_t*)(bp + tb + PB_LO + so) = *(uint32_t*)&lp;
        }
    };

    // prologue: fill buffer 0
    genP(0u, 0);
    loadW(0u, 0);

    for (int c = 0; c < 64; ++c) {
        uint32_t tb = (uint32_t)(c & 1) * BUFSZ;
        uint32_t nb = tb ^ BUFSZ;
        CP_WAIT0();            // W(c) in smem
        __syncthreads();       // P(c) visible; all warps done with MMA(c-1)
        if (c < 63) loadW(nb, c+1);   // overlaps MMA(c) + genP(c+1)
        // ---- MMA(c): warp tile 64(M) x 32(N), 3 bf16 terms ----
        #pragma unroll
        for (int kt=0;kt<4;kt++){
            uint32_t ah[4][4], al[4][4], bh[4][2], bl[4][2];
            uint32_t kb = (uint32_t)(kt*32 + (lane>>4)*16);
            #pragma unroll
            for (int mt=0;mt<4;mt++){
                uint32_t off = SW128((uint32_t)((wm*64 + mt*16 + (lane&15))*128) + kb);
                ldsm4(ah[mt], sb + tb + PB_HI + off);
                ldsm4(al[mt], sb + tb + PB_LO + off);
            }
            #pragma unroll
            for (int pp=0;pp<2;pp++){
                uint32_t off = SW128((uint32_t)((wn*32 + pp*16 + (lane&15))*128) + kb);
                uint32_t t0[4], t1[4];
                ldsm4(t0, sb + tb + WB_HI + off);
                ldsm4(t1, sb + tb + WB_LO + off);
                bh[pp*2  ][0]=t0[0]; bh[pp*2  ][1]=t0[2];
                bh[pp*2+1][0]=t0[1]; bh[pp*2+1][1]=t0[3];
                bl[pp*2  ][0]=t1[0]; bl[pp*2  ][1]=t1[2];
                bl[pp*2+1][0]=t1[1]; bl[pp*2+1][1]=t1[3];
            }
            #pragma unroll
            for (int mt=0;mt<4;mt++)
                #pragma unroll
                for (int nt=0;nt<4;nt++){
                    mma16816(acc[mt][nt], ah[mt], bh[nt]);
                    mma16816(acc[mt][nt], ah[mt], bl[nt]);
                    mma16816(acc[mt][nt], al[mt], bh[nt]);
                }
        }
        if (c < 63) genP(nb, c+1);    // next P while tensor pipe drains
    }
    // ---- row sums -> 1/l ----
    float full = rsum + __shfl_xor_sync(0xffffffffu, rsum, 1);
    if (!(tid & 1)) sml[r] = 1.0f / full;
    __syncthreads();
    // ---- epilogue: normalize, elu, store ----
    #pragma unroll
    for (int mt=0;mt<4;mt++){
        int r0 = wm*64 + mt*16 + (lane>>2);
        float il0 = sml[r0], il1 = sml[r0+8];
        #pragma unroll
        for (int nt=0;nt<4;nt++){
            int fcol = wn*32 + nt*8 + (lane&3)*2;
            float2 v0, v1;
            v0.x = eluf(acc[mt][nt][0]*il0);
            v0.y = eluf(acc[mt][nt][1]*il0);
            v1.x = eluf(acc[mt][nt][2]*il1);
            v1.y = eluf(acc[mt][nt][3]*il1);
            *(float2*)(outp + (size_t)(i0+r0  )*KX_ + h*D_ + fcol) = v0;
            *(float2*)(outp + (size_t)(i0+r0+8)*KX_ + h*D_ + fcol) = v1;
        }
    }
}

// ---------------- launch ----------------
extern "C" void kernel_launch(void* const* d_in, const int* in_sizes, int n_in,
                              void* d_out, int out_size) {
    const float* chems = (const float*)d_in[0];
    const int*   adj   = (const int*)  d_in[1];
    const float* W1    = (const float*)d_in[2];
    const float* a1    = (const float*)d_in[3];
    const float* W2    = (const float*)d_in[4];
    const float* a2    = (const float*)d_in[5];
    float* out = (float*)d_out;

    cudaFuncSetAttribute(attn_hmma, cudaFuncAttributeMaxDynamicSharedMemorySize, SMEM_DYN);

    pack_adj<<<1024, 256>>>(adj);

    // stage 1
    gemm_wh<<<dim3(N_/128,1,H_), 256>>>(chems, D_, (long)N_*D_, W1, D_, 1);
    cvt_whT<<<dim3(N_/32, D_/32, H_), 256>>>();
    srcdst_k<<<dim3(N_/8, H_), 256>>>(a1);
    attn_hmma<<<dim3(N_/128, H_), 256, SMEM_DYN>>>(nullptr, 1);

    // stage 2
    gemm_wh<<<dim3(N_/128,1,H_), 256>>>(nullptr, KX_, 0, W2, KX_, 2);
    cvt_whT<<<dim3(N_/32, D_/32, H_), 256>>>();
    srcdst_k<<<dim3(N_/8, H_), 256>>>(a2);
    attn_hmma<<<dim3(N_/128, H_), 256, SMEM_DYN>>>(out, 2);
}

// round 5
// speedup vs baseline: 3.2800x; 1.1577x over previous
#include <cuda_runtime.h>
#include <cuda_bf16.h>
#include <cstdint>

#define H_ 4
#define N_ 4096
#define D_ 128
#define KX_ 512            // H * D
#define NW_ (N_/32)        // 128 mask words per row
#define ALPHA_ 0.2f

// ---------------- device scratch ----------------
__device__ float          g_Wh[H_*N_*D_];        // 8 MB fp32 Wh
__device__ float          g_x [N_*KX_];          // 8 MB stage-1 output
__device__ unsigned       g_adjb[N_*NW_];        // 2 MB adjacency bitmask
__device__ float2         g_EFs[H_*N_];          // rows: {e^s, e^.2s}
__device__ float2         g_EFd[H_*N_];          // cols: {e^d, e^.2d}
__device__ __nv_bfloat16  g_whT_hi[H_*D_*N_];    // 4 MB Wh^T hi [h][f][j]
__device__ __nv_bfloat16  g_whT_lo[H_*D_*N_];    // 4 MB Wh^T lo

// ---------------- helpers ----------------
__device__ __forceinline__ uint32_t smem_u32(const void* p){
    uint32_t a;
    asm("{ .reg .u64 t; cvta.to.shared.u64 t, %1; cvt.u32.u64 %0, t; }"
        : "=r"(a) : "l"(p));
    return a;
}
#define SW128(o) ((o) ^ (((o) >> 3) & 0x70))

__device__ __forceinline__ unsigned long long splat2(float x){
    unsigned long long r;
    asm("mov.b64 %0, {%1, %1};" : "=l"(r) : "f"(x));
    return r;
}
__device__ __forceinline__ void dfma2(unsigned long long& c,
                                      unsigned long long a, unsigned long long b){
    asm("fma.rn.f32x2 %0, %1, %2, %0;" : "+l"(c) : "l"(a), "l"(b));
}
__device__ __forceinline__ float2 unpack2(unsigned long long v){
    float2 f;
    asm("mov.b64 {%0, %1}, %2;" : "=f"(f.x), "=f"(f.y) : "l"(v));
    return f;
}
__device__ __forceinline__ float eluf(float x){ return x > 0.f ? x : expm1f(x); }

__device__ __forceinline__ float fexp(float x){
    const float L2E   = 1.4426950408889634f;
    const float MAGIC = 12582912.0f;
    float t  = x * L2E;
    float kf = t + MAGIC;
    int   ki = __float_as_int(kf);
    float km = kf - MAGIC;
    float f  = t - km;
    float p  = 1.33335581e-3f;
    p = fmaf(p, f, 9.61812910e-3f);
    p = fmaf(p, f, 5.55041087e-2f);
    p = fmaf(p, f, 2.40226507e-1f);
    p = fmaf(p, f, 6.93147180e-1f);
    p = fmaf(p, f, 1.0f);
    return __int_as_float(__float_as_int(p) + (int)((unsigned)ki << 23));
}

__device__ __forceinline__ void ldsm4(uint32_t* r, uint32_t addr){
    asm volatile("ldmatrix.sync.aligned.m8n8.x4.shared.b16 {%0,%1,%2,%3}, [%4];"
        : "=r"(r[0]),"=r"(r[1]),"=r"(r[2]),"=r"(r[3]) : "r"(addr));
}
__device__ __forceinline__ void mma16816(float* c, const uint32_t* a, const uint32_t* b){
    asm volatile("mma.sync.aligned.m16n8k16.row.col.f32.bf16.bf16.f32 "
        "{%0,%1,%2,%3}, {%4,%5,%6,%7}, {%8,%9}, {%0,%1,%2,%3};"
        : "+f"(c[0]),"+f"(c[1]),"+f"(c[2]),"+f"(c[3])
        : "r"(a[0]),"r"(a[1]),"r"(a[2]),"r"(a[3]), "r"(b[0]),"r"(b[1]));
}
__device__ __forceinline__ void cpasync16(uint32_t dst, const void* src){
    asm volatile("cp.async.cg.shared.global [%0], [%1], 16;" :: "r"(dst), "l"(src));
}
#define CP_COMMIT() asm volatile("cp.async.commit_group;" ::: "memory")
#define CP_WAIT0()  asm volatile("cp.async.wait_group 0;"  ::: "memory")

// ---------------- K0: pack adj ----------------
__global__ void pack_adj(const int* __restrict__ adj) {
    int gwarp  = (blockIdx.x*blockDim.x + threadIdx.x) >> 5;
    int lane   = threadIdx.x & 31;
    int nwarps = (gridDim.x*blockDim.x) >> 5;
    for (int w = gwarp; w < N_*NW_; w += nwarps) {
        int v = adj[(size_t)w*32 + lane];
        unsigned bits = __ballot_sync(0xffffffffu, v > 0);
        if (lane == 0) g_adjb[w] = bits;
    }
}

// ---------------- K1: Wh = X @ W (FFMA2) ----------------
__global__ __launch_bounds__(256) void gemm_wh(
    const float* __restrict__ A_ext, int lda, long aHeadStride,
    const float* __restrict__ B, int K, int stage)
{
    __shared__ float As[16][128];
    __shared__ float Bs[16][128];
    int h = blockIdx.z;
    const float* A  = (stage == 2) ? g_x : A_ext;
    const float* Ah = A + (long)h * aHeadStride;
    const float* Bh = B + (long)h * K * D_;
    float*       Ch = g_Wh + (size_t)h * N_ * D_;
    int m0 = blockIdx.x * 128;
    int tid = threadIdx.x;
    int tx = tid & 15, ty = tid >> 4;
    unsigned long long acc2[8][4];
    #pragma unroll
    for (int i=0;i<8;i++)
        #pragma unroll
        for (int j=0;j<4;j++) acc2[i][j]=0ull;

    for (int k0 = 0; k0 < K; k0 += 16) {
        #pragma unroll
        for (int l=0;l<2;l++){
            int idx = tid + l*256;
            int row = idx >> 2;
            int c4  = idx & 3;
            float4 v = *(const float4*)&Ah[(size_t)(m0+row)*lda + k0 + c4*4];
            As[c4*4+0][row]=v.x; As[c4*4+1][row]=v.y;
            As[c4*4+2][row]=v.z; As[c4*4+3][row]=v.w;
        }
        #pragma unroll
        for (int l=0;l<2;l++){
            int idx = tid + l*256;
            int row = idx >> 5;
            int c4  = idx & 31;
            *(float4*)&Bs[row][c4*4] = *(const float4*)&Bh[(size_t)(k0+row)*D_ + c4*4];
        }
        __syncthreads();
        #pragma unroll
        for (int k=0;k<16;k++){
            float a[8];
            *(float4*)(a)   = *(const float4*)&As[k][ty*8];
            *(float4*)(a+4) = *(const float4*)&As[k][ty*8+4];
            const unsigned long long* bpr = (const unsigned long long*)&Bs[k][tx*8];
            unsigned long long b0=bpr[0], b1=bpr[1], b2=bpr[2], b3=bpr[3];
            #pragma unroll
            for (int i=0;i<8;i++){
                unsigned long long as = splat2(a[i]);
                dfma2(acc2[i][0],as,b0); dfma2(acc2[i][1],as,b1);
                dfma2(acc2[i][2],as,b2); dfma2(acc2[i][3],as,b3);
            }
        }
        __syncthreads();
    }
    #pragma unroll
    for (int i=0;i<8;i++){
        size_t row = m0 + ty*8 + i;
        float v[8];
        #pragma unroll
        for (int jp=0;jp<4;jp++){
            float2 f = unpack2(acc2[i][jp]);
            v[jp*2] = f.x; v[jp*2+1] = f.y;
        }
        *(float4*)&Ch[row*D_ + tx*8    ] = *(const float4*)&v[0];
        *(float4*)&Ch[row*D_ + tx*8 + 4] = *(const float4*)&v[4];
    }
}

// ---------------- K1b: Wh^T -> bf16 hi/lo ----------------
__global__ __launch_bounds__(256) void cvt_whT() {
    __shared__ float ts[32][33];
    int h  = blockIdx.z;
    int j0 = blockIdx.x * 32;
    int f0 = blockIdx.y * 32;
    int tx = threadIdx.x & 31, ty = threadIdx.x >> 5;
    const float* Wh = g_Wh + (size_t)h*N_*D_;
    #pragma unroll
    for (int r=0;r<4;r++){
        int j = j0 + ty + r*8;
        ts[ty + r*8][tx] = Wh[(size_t)j*D_ + f0 + tx];
    }
    __syncthreads();
    #pragma unroll
    for (int r=0;r<4;r++){
        int f = f0 + ty + r*8;
        float v = ts[tx][ty + r*8];
        __nv_bfloat16 hi = __float2bfloat16(v);
        __nv_bfloat16 lo = __float2bfloat16(v - __bfloat162float(hi));
        size_t o = ((size_t)(h*D_ + f))*N_ + j0 + tx;
        g_whT_hi[o] = hi;
        g_whT_lo[o] = lo;
    }
}

// ---------------- K2: src/dst dots -> per-node exp factors ---------------
__global__ void srcdst_k(const float* __restrict__ avec) {
    int h = blockIdx.y;
    int warp = threadIdx.x >> 5, lane = threadIdx.x & 31;
    int i = blockIdx.x*8 + warp;
    const float* wh = g_Wh + ((size_t)h*N_ + i)*D_;
    const float* av = avec + h*2*D_;
    float4 w4 = *(const float4*)&wh[lane*4];
    float4 s4 = *(const float4*)&av[lane*4];
    float4 d4 = *(const float4*)&av[D_ + lane*4];
    float s = w4.x*s4.x + w4.y*s4.y + w4.z*s4.z + w4.w*s4.w;
    float d = w4.x*d4.x + w4.y*d4.y + w4.z*d4.z + w4.w*d4.w;
    #pragma unroll
    for (int o=16;o>0;o>>=1){
        s += __shfl_down_sync(0xffffffffu, s, o);
        d += __shfl_down_sync(0xffffffffu, d, o);
    }
    if (lane==0){
        g_EFs[h*N_+i] = make_float2(fexp(s), fexp(ALPHA_*s));
        g_EFd[h*N_+i] = make_float2(fexp(d), fexp(ALPHA_*d));
    }
}

// ---------------- K3: warp-specialized attn --------------------------
// 512 thr: warps 0-7 = MMA consumers (tile 64x32 each, grid 2x4),
//          warps 8-15 = producers (P gen + cp.async W loads).
#define PB_HI 0
#define PB_LO 16384
#define WB_HI 32768
#define WB_LO 49152
#define BUFSZ 65536
#define OFF_L (2*BUFSZ)
#define SMEM_DYN (2*BUFSZ + 512 + 1024)

__global__ __launch_bounds__(512,1) void attn_hmma(float* __restrict__ out_ext, int stage) {
    extern __shared__ char dsm[];
    uint32_t raw = smem_u32(dsm);
    uint32_t sb  = (raw + 1023) & ~1023u;
    char* bp = dsm + (sb - raw);
    float* sml = (float*)(bp + OFF_L);

    int h = blockIdx.y, i0 = blockIdx.x*128;
    int tid = threadIdx.x, lane = tid & 31, wid = tid >> 5;
    float* outp = (stage==1) ? g_x : out_ext;
    bool producer = (wid >= 8);

    if (producer) {
        // ---------------- producer path ----------------
        int ptid = tid - 256;
        int r = ptid >> 1, jh = ptid & 1;
        float2 efs = g_EFs[h*N_ + i0 + r];
        float Ei = efs.x, Fi = efs.y;
        const float2*   efd    = g_EFd + h*N_;
        const unsigned* adjrow = g_adjb + (size_t)(i0+r)*NW_;
        const char* whh = (const char*)(g_whT_hi + (size_t)h*D_*N_);
        const char* whl = (const char*)(g_whT_lo + (size_t)h*D_*N_);
        float rsum = 0.f;

        auto loadW = [&](uint32_t tb, int c){
            int j0 = c * 64;
            #pragma unroll
            for (int l=0;l<4;l++){
                int idx = ptid + l*256;
                int f = idx >> 3, seg = idx & 7;
                size_t go = (((size_t)f*N_ + j0) << 1) + (size_t)seg*16;
                uint32_t so = SW128((uint32_t)(f*128 + seg*16));
                cpasync16(sb + tb + WB_HI + so, whh + go);
                cpasync16(sb + tb + WB_LO + so, whl + go);
            }
            CP_COMMIT();
        };
        auto genP = [&](uint32_t tb, int c){
            int j0 = c * 64;
            unsigned w = adjrow[(j0>>5) + jh];
            const float4* efp = (const float4*)(efd + j0 + jh*32);
            uint32_t rb = (uint32_t)(r*128 + jh*64);
            #pragma unroll
            for (int q=0;q<16;q++){
                float4 e01 = efp[q];
                float p0 = fmaxf(Ei*e01.x, Fi*e01.y);
                float p1 = fmaxf(Ei*e01.z, Fi*e01.w);
                p0 = ((w>>(2*q  ))&1u) ? p0 : 0.f;
                p1 = ((w>>(2*q+1))&1u) ? p1 : 0.f;
                rsum += p0 + p1;
                __nv_bfloat162 hp = __floats2bfloat162_rn(p0, p1);
                uint32_t hb = *(uint32_t*)&hp;
                float h0 = __uint_as_float(hb << 16);
                float h1 = __uint_as_float(hb & 0xffff0000u);
                __nv_bfloat162 lp = __floats2bfloat162_rn(p0 - h0, p1 - h1);
                uint32_t so = SW128(rb + q*4);
                *(uint32_t*)(bp + tb + PB_HI + so) = hb;
                *(uint32_t*)(bp + tb + PB_LO + so) = *(uint32_t*)&lp;
            }
        };

        genP(0u, 0);
        loadW(0u, 0);
        CP_WAIT0();
        __syncthreads();                 // buffer 0 ready
        for (int c = 0; c < 64; ++c) {
            uint32_t nb = (uint32_t)(~c & 1) * BUFSZ;
            if (c < 63){
                genP(nb, c+1);
                loadW(nb, c+1);
                CP_WAIT0();
            }
            __syncthreads();             // hand buffer(c+1) to consumers; they finished buffer(c)
        }
        float full = rsum + __shfl_xor_sync(0xffffffffu, rsum, 1);
        if (!(ptid & 1)) sml[r] = 1.0f / full;
        __syncthreads();
        // producers done (consumers do epilogue)
    } else {
        // ---------------- consumer path ----------------
        int wm = wid >> 2, wn = wid & 3;
        float acc[4][4][4];
        #pragma unroll
        for (int a=0;a<4;a++)
            #pragma unroll
            for (int b=0;b<4;b++)
                #pragma unroll
                for (int c=0;c<4;c++) acc[a][b][c]=0.f;

        __syncthreads();                 // buffer 0 ready
        for (int c = 0; c < 64; ++c) {
            uint32_t tb = (uint32_t)(c & 1) * BUFSZ;
            #pragma unroll
            for (int kt=0;kt<4;kt++){
                uint32_t kb = (uint32_t)(kt*32 + (lane>>4)*16);
                uint32_t bh[4][2], bl[4][2];
                #pragma unroll
                for (int pp=0;pp<2;pp++){
                    uint32_t off = SW128((uint32_t)((wn*32 + pp*16 + (lane&15))*128) + kb);
                    uint32_t t0[4], t1[4];
                    ldsm4(t0, sb + tb + WB_HI + off);
                    ldsm4(t1, sb + tb + WB_LO + off);
                    bh[pp*2  ][0]=t0[0]; bh[pp*2  ][1]=t0[2];
                    bh[pp*2+1][0]=t0[1]; bh[pp*2+1][1]=t0[3];
                    bl[pp*2  ][0]=t1[0]; bl[pp*2  ][1]=t1[2];
                    bl[pp*2+1][0]=t1[1]; bl[pp*2+1][1]=t1[3];
                }
                #pragma unroll
                for (int mt=0;mt<4;mt++){
                    uint32_t off = SW128((uint32_t)((wm*64 + mt*16 + (lane&15))*128) + kb);
                    uint32_t ah[4], al[4];
                    ldsm4(ah, sb + tb + PB_HI + off);
                    ldsm4(al, sb + tb + PB_LO + off);
                    #pragma unroll
                    for (int nt=0;nt<4;nt++){
                        mma16816(acc[mt][nt], ah, bh[nt]);
                        mma16816(acc[mt][nt], ah, bl[nt]);
                        mma16816(acc[mt][nt], al, bh[nt]);
                    }
                }
            }
            __syncthreads();             // done with buffer(c); producers handed buffer(c+1)
        }
        __syncthreads();                 // sml ready
        #pragma unroll
        for (int mt=0;mt<4;mt++){
            int r0 = wm*64 + mt*16 + (lane>>2);
            float il0 = sml[r0], il1 = sml[r0+8];
            #pragma unroll
            for (int nt=0;nt<4;nt++){
                int fcol = wn*32 + nt*8 + (lane&3)*2;
                float2 v0, v1;
                v0.x = eluf(acc[mt][nt][0]*il0);
                v0.y = eluf(acc[mt][nt][1]*il0);
                v1.x = eluf(acc[mt][nt][2]*il1);
                v1.y = eluf(acc[mt][nt][3]*il1);
                *(float2*)(outp + (size_t)(i0+r0  )*KX_ + h*D_ + fcol) = v0;
                *(float2*)(outp + (size_t)(i0+r0+8)*KX_ + h*D_ + fcol) = v1;
            }
        }
    }
}

// ---------------- launch ----------------
extern "C" void kernel_launch(void* const* d_in, const int* in_sizes, int n_in,
                              void* d_out, int out_size) {
    const float* chems = (const float*)d_in[0];
    const int*   adj   = (const int*)  d_in[1];
    const float* W1    = (const float*)d_in[2];
    const float* a1    = (const float*)d_in[3];
    const float* W2    = (const float*)d_in[4];
    const float* a2    = (const float*)d_in[5];
    float* out = (float*)d_out;

    cudaFuncSetAttribute(attn_hmma, cudaFuncAttributeMaxDynamicSharedMemorySize, SMEM_DYN);

    pack_adj<<<1024, 256>>>(adj);

    // stage 1
    gemm_wh<<<dim3(N_/128,1,H_), 256>>>(chems, D_, (long)N_*D_, W1, D_, 1);
    cvt_whT<<<dim3(N_/32, D_/32, H_), 256>>>();
    srcdst_k<<<dim3(N_/8, H_), 256>>>(a1);
    attn_hmma<<<dim3(N_/128, H_), 512, SMEM_DYN>>>(nullptr, 1);

    // stage 2
    gemm_wh<<<dim3(N_/128,1,H_), 256>>>(nullptr, KX_, 0, W2, KX_, 2);
    cvt_whT<<<dim3(N_/32, D_/32, H_), 256>>>();
    srcdst_k<<<dim3(N_/8, H_), 256>>>(a2);
    attn_hmma<<<dim3(N_/128, H_), 512, SMEM_DYN>>>(out, 2);
}

// round 7
// speedup vs baseline: 3.5572x; 1.0845x over previous
#include <cuda_runtime.h>
#include <cuda_bf16.h>
#include <cstdint>

#define H_ 4
#define N_ 4096
#define D_ 128
#define KX_ 512            // H * D
#define NW_ (N_/32)        // 128 mask words per row
#define ALPHA_ 0.2f

// ---------------- device scratch (uint4-backed for 16B alignment) --------
__device__ float    g_Wh[H_*N_*D_];          // 8 MB fp32 Wh
__device__ unsigned g_adjb[N_*NW_];          // 2 MB adjacency bitmask
__device__ float2   g_EFs[H_*N_];            // rows: {e^s, e^.2s}
__device__ float2   g_EFd[H_*N_];            // cols: {e^d, e^.2d}
__device__ uint4    g_whT_hi4[H_*D_*N_/8];   // Wh^T hi [h][f][j]
__device__ uint4    g_whT_lo4[H_*D_*N_/8];
__device__ uint4    g_ch_hi4 [H_*N_*D_/8];   // chems hi/lo
__device__ uint4    g_ch_lo4 [H_*N_*D_/8];
__device__ uint4    g_x_hi4  [N_*KX_/8];     // stage-1 output hi/lo
__device__ uint4    g_x_lo4  [N_*KX_/8];
__device__ uint4    g_W1T_hi4[H_*D_*D_/8];   // W1^T [h][dout][k]
__device__ uint4    g_W1T_lo4[H_*D_*D_/8];
__device__ uint4    g_W2T_hi4[H_*D_*KX_/8];  // W2^T [h][dout][k]
__device__ uint4    g_W2T_lo4[H_*D_*KX_/8];

// device-code-only views (NEVER pass these as kernel args from host!)
#define g_whT_hi ((__nv_bfloat16*)g_whT_hi4)
#define g_whT_lo ((__nv_bfloat16*)g_whT_lo4)
#define g_ch_hi  ((__nv_bfloat16*)g_ch_hi4)
#define g_ch_lo  ((__nv_bfloat16*)g_ch_lo4)
#define g_x_hi   ((__nv_bfloat16*)g_x_hi4)
#define g_x_lo   ((__nv_bfloat16*)g_x_lo4)
#define g_W1T_hi ((__nv_bfloat16*)g_W1T_hi4)
#define g_W1T_lo ((__nv_bfloat16*)g_W1T_lo4)
#define g_W2T_hi ((__nv_bfloat16*)g_W2T_hi4)
#define g_W2T_lo ((__nv_bfloat16*)g_W2T_lo4)

// ---------------- helpers ----------------
__device__ __forceinline__ uint32_t smem_u32(const void* p){
    uint32_t a;
    asm("{ .reg .u64 t; cvta.to.shared.u64 t, %1; cvt.u32.u64 %0, t; }"
        : "=r"(a) : "l"(p));
    return a;
}
#define SW128(o) ((o) ^ (((o) >> 3) & 0x70))

__device__ __forceinline__ float eluf(float x){ return x > 0.f ? x : expm1f(x); }

__device__ __forceinline__ float fexp(float x){
    const float L2E   = 1.4426950408889634f;
    const float MAGIC = 12582912.0f;
    float t  = x * L2E;
    float kf = t + MAGIC;
    int   ki = __float_as_int(kf);
    float km = kf - MAGIC;
    float f  = t - km;
    float p  = 1.33335581e-3f;
    p = fmaf(p, f, 9.61812910e-3f);
    p = fmaf(p, f, 5.55041087e-2f);
    p = fmaf(p, f, 2.40226507e-1f);
    p = fmaf(p, f, 6.93147180e-1f);
    p = fmaf(p, f, 1.0f);
    return __int_as_float(__float_as_int(p) + (int)((unsigned)ki << 23));
}

__device__ __forceinline__ void ldsm4(uint32_t* r, uint32_t addr){
    asm volatile("ldmatrix.sync.aligned.m8n8.x4.shared.b16 {%0,%1,%2,%3}, [%4];"
        : "=r"(r[0]),"=r"(r[1]),"=r"(r[2]),"=r"(r[3]) : "r"(addr));
}
__device__ __forceinline__ void mma16816(float* c, const uint32_t* a, const uint32_t* b){
    asm volatile("mma.sync.aligned.m16n8k16.row.col.f32.bf16.bf16.f32 "
        "{%0,%1,%2,%3}, {%4,%5,%6,%7}, {%8,%9}, {%0,%1,%2,%3};"
        : "+f"(c[0]),"+f"(c[1]),"+f"(c[2]),"+f"(c[3])
        : "r"(a[0]),"r"(a[1]),"r"(a[2]),"r"(a[3]), "r"(b[0]),"r"(b[1]));
}
__device__ __forceinline__ void cpasync16(uint32_t dst, const void* src){
    asm volatile("cp.async.cg.shared.global [%0], [%1], 16;" :: "r"(dst), "l"(src));
}
#define CP_COMMIT() asm volatile("cp.async.commit_group;" ::: "memory")
#define CP_WAIT0()  asm volatile("cp.async.wait_group 0;"  ::: "memory")

__device__ __forceinline__ uint32_t pack_hi(float a, float b, float& ra, float& rb){
    __nv_bfloat162 hp = __floats2bfloat162_rn(a, b);
    uint32_t hb = *(uint32_t*)&hp;
    ra = a - __uint_as_float(hb << 16);
    rb = b - __uint_as_float(hb & 0xffff0000u);
    return hb;
}

// ---------------- K0: pack adj ----------------
__global__ void pack_adj(const int* __restrict__ adj) {
    int gwarp  = (blockIdx.x*blockDim.x + threadIdx.x) >> 5;
    int lane   = threadIdx.x & 31;
    int nwarps = (gridDim.x*blockDim.x) >> 5;
    for (int w = gwarp; w < N_*NW_; w += nwarps) {
        int v = adj[(size_t)w*32 + lane];
        unsigned bits = __ballot_sync(0xffffffffu, v > 0);
        if (lane == 0) g_adjb[w] = bits;
    }
}

// ---------------- K0b: split chems -> bf16 hi/lo ----------------
__global__ void split_ch(const float* __restrict__ c){
    size_t i = ((size_t)blockIdx.x*blockDim.x + threadIdx.x)*4;
    float4 v = *(const float4*)(c + i);
    float rx,ry,rz,rw;
    uint32_t h0 = pack_hi(v.x, v.y, rx, ry);
    uint32_t h1 = pack_hi(v.z, v.w, rz, rw);
    __nv_bfloat162 l0 = __floats2bfloat162_rn(rx, ry);
    __nv_bfloat162 l1 = __floats2bfloat162_rn(rz, rw);
    uint2 ho = make_uint2(h0, h1);
    uint2 lo = make_uint2(*(uint32_t*)&l0, *(uint32_t*)&l1);
    *(uint2*)((char*)g_ch_hi + i*2) = ho;
    *(uint2*)((char*)g_ch_lo + i*2) = lo;
}

// ---------------- K0c: W [h][K][128] -> W^T hi/lo [h][128][K] ----------
__global__ void split_WT(const float* __restrict__ W, int K, int which){
    __shared__ float ts[32][33];
    __nv_bfloat16* Thi = (which==1) ? g_W1T_hi : g_W2T_hi;
    __nv_bfloat16* Tlo = (which==1) ? g_W1T_lo : g_W2T_lo;
    int h = blockIdx.z, k0 = blockIdx.x*32, f0 = blockIdx.y*32;
    int tx = threadIdx.x & 31, ty = threadIdx.x >> 5;
    const float* Wh = W + (size_t)h*K*128;
    #pragma unroll
    for (int r=0;r<4;r++)
        ts[ty + r*8][tx] = Wh[(size_t)(k0 + ty + r*8)*128 + f0 + tx];
    __syncthreads();
    #pragma unroll
    for (int r=0;r<4;r++){
        int f = f0 + ty + r*8;
        float v = ts[tx][ty + r*8];                 // = W[k0+tx][f]
        __nv_bfloat16 hi = __float2bfloat16(v);
        __nv_bfloat16 lo = __float2bfloat16(v - __bfloat162float(hi));
        size_t o = ((size_t)h*128 + f)*K + k0 + tx;
        Thi[o] = hi; Tlo[o] = lo;
    }
}

// ---------------- K1: Wh = X @ W via 3-term bf16 HMMA -------------------
#define GA_HI 0
#define GA_LO 32768
#define GB_HI 65536
#define GB_LO 98304
#define SMEMG (131072 + 1024)

__global__ __launch_bounds__(256,1) void gemm_hmma(int stage, int K)
{
    extern __shared__ char dsm[];
    uint32_t raw = smem_u32(dsm);
    uint32_t sb  = (raw + 1023) & ~1023u;

    // bind device globals INSIDE device code (host-passed symbols are UB)
    const __nv_bfloat16 *Ahi, *Alo, *BThi, *BTlo;
    long aHeadStride;
    if (stage == 1){
        Ahi = g_ch_hi; Alo = g_ch_lo;
        BThi = g_W1T_hi; BTlo = g_W1T_lo;
        aHeadStride = (long)N_*D_;
    } else {
        Ahi = g_x_hi; Alo = g_x_lo;
        BThi = g_W2T_hi; BTlo = g_W2T_lo;
        aHeadStride = 0;
    }

    int h = blockIdx.y, m0 = blockIdx.x*128;
    int tid = threadIdx.x, lane = tid & 31, wid = tid >> 5;
    int wm = wid >> 2, wn = wid & 3;
    const char* pAhi = (const char*)(Ahi + (size_t)h*aHeadStride + (size_t)m0*K);
    const char* pAlo = (const char*)(Alo + (size_t)h*aHeadStride + (size_t)m0*K);
    const char* pBhi = (const char*)(BThi + (size_t)h*128*K);
    const char* pBlo = (const char*)(BTlo + (size_t)h*128*K);
    long rs = (long)K*2;

    float acc[4][4][4];
    #pragma unroll
    for (int a=0;a<4;a++)
        #pragma unroll
        for (int b=0;b<4;b++)
            #pragma unroll
            for (int c=0;c<4;c++) acc[a][b][c]=0.f;

    auto ldpart = [&](uint32_t dstBase, const char* g, long colByte){
        #pragma unroll
        for (int l=0;l<8;l++){
            int idx = tid + l*256;               // 0..2047
            int row = idx >> 4;
            int s16 = idx & 15;                  // 16B segment in 256B row-chunk
            uint32_t so = SW128((uint32_t)(row*128 + (s16&7)*16)) + (uint32_t)(s16>>3)*16384;
            cpasync16(sb + dstBase + so, g + (long)row*rs + colByte + s16*16);
        }
    };

    int nk = K >> 7;                             // 128-K chunks
    for (int kc = 0; kc < nk; ++kc){
        long cb = (long)kc*256;
        ldpart(GA_HI, pAhi, cb);
        ldpart(GA_LO, pAlo, cb);
        ldpart(GB_HI, pBhi, cb);
        ldpart(GB_LO, pBlo, cb);
        CP_COMMIT();
        CP_WAIT0();
        __syncthreads();
        #pragma unroll
        for (int kt=0;kt<8;kt++){
            uint32_t subo = (uint32_t)(kt>>2)*16384;
            uint32_t kb = (uint32_t)((kt&3)*32 + (lane>>4)*16);
            uint32_t bh[4][2], bl[4][2];
            #pragma unroll
            for (int pp=0;pp<2;pp++){
                uint32_t off = SW128((uint32_t)((wn*32 + pp*16 + (lane&15))*128) + kb) + subo;
                uint32_t t0[4], t1[4];
                ldsm4(t0, sb + GB_HI + off);
                ldsm4(t1, sb + GB_LO + off);
                bh[pp*2  ][0]=t0[0]; bh[pp*2  ][1]=t0[2];
                bh[pp*2+1][0]=t0[1]; bh[pp*2+1][1]=t0[3];
                bl[pp*2  ][0]=t1[0]; bl[pp*2  ][1]=t1[2];
                bl[pp*2+1][0]=t1[1]; bl[pp*2+1][1]=t1[3];
            }
            #pragma unroll
            for (int mt=0;mt<4;mt++){
                uint32_t off = SW128((uint32_t)((wm*64 + mt*16 + (lane&15))*128) + kb) + subo;
                uint32_t ah[4], al[4];
                ldsm4(ah, sb + GA_HI + off);
                ldsm4(al, sb + GA_LO + off);
                #pragma unroll
                for (int nt=0;nt<4;nt++){
                    mma16816(acc[mt][nt], ah, bh[nt]);
                    mma16816(acc[mt][nt], ah, bl[nt]);
                    mma16816(acc[mt][nt], al, bh[nt]);
                }
            }
        }
        __syncthreads();
    }
    float* Ch = g_Wh + (size_t)h*N_*D_;
    #pragma unroll
    for (int mt=0;mt<4;mt++){
        int r0 = m0 + wm*64 + mt*16 + (lane>>2);
        #pragma unroll
        for (int nt=0;nt<4;nt++){
            int fcol = wn*32 + nt*8 + (lane&3)*2;
            *(float2*)(Ch + (size_t)r0*D_ + fcol)     = make_float2(acc[mt][nt][0], acc[mt][nt][1]);
            *(float2*)(Ch + (size_t)(r0+8)*D_ + fcol) = make_float2(acc[mt][nt][2], acc[mt][nt][3]);
        }
    }
}

// ---------------- K1b: Wh^T -> bf16 hi/lo ----------------
__global__ __launch_bounds__(256) void cvt_whT() {
    __shared__ float ts[32][33];
    int h  = blockIdx.z;
    int j0 = blockIdx.x * 32;
    int f0 = blockIdx.y * 32;
    int tx = threadIdx.x & 31, ty = threadIdx.x >> 5;
    const float* Wh = g_Wh + (size_t)h*N_*D_;
    #pragma unroll
    for (int r=0;r<4;r++){
        int j = j0 + ty + r*8;
        ts[ty + r*8][tx] = Wh[(size_t)j*D_ + f0 + tx];
    }
    __syncthreads();
    #pragma unroll
    for (int r=0;r<4;r++){
        int f = f0 + ty + r*8;
        float v = ts[tx][ty + r*8];
        __nv_bfloat16 hi = __float2bfloat16(v);
        __nv_bfloat16 lo = __float2bfloat16(v - __bfloat162float(hi));
        size_t o = ((size_t)(h*D_ + f))*N_ + j0 + tx;
        g_whT_hi[o] = hi;
        g_whT_lo[o] = lo;
    }
}

// ---------------- K2: src/dst dots -> per-node exp factors ---------------
__global__ void srcdst_k(const float* __restrict__ avec) {
    int h = blockIdx.y;
    int warp = threadIdx.x >> 5, lane = threadIdx.x & 31;
    int i = blockIdx.x*8 + warp;
    const float* wh = g_Wh + ((size_t)h*N_ + i)*D_;
    const float* av = avec + h*2*D_;
    float4 w4 = *(const float4*)&wh[lane*4];
    float4 s4 = *(const float4*)&av[lane*4];
    float4 d4 = *(const float4*)&av[D_ + lane*4];
    float s = w4.x*s4.x + w4.y*s4.y + w4.z*s4.z + w4.w*s4.w;
    float d = w4.x*d4.x + w4.y*d4.y + w4.z*d4.z + w4.w*d4.w;
    #pragma unroll
    for (int o=16;o>0;o>>=1){
        s += __shfl_down_sync(0xffffffffu, s, o);
        d += __shfl_down_sync(0xffffffffu, d, o);
    }
    if (lane==0){
        g_EFs[h*N_+i] = make_float2(fexp(s), fexp(ALPHA_*s));
        g_EFd[h*N_+i] = make_float2(fexp(d), fexp(ALPHA_*d));
    }
}

// ---------------- K3: warp-specialized attn ------------------------------
#define PB_HI 0
#define PB_LO 16384
#define WB_HI 32768
#define WB_LO 49152
#define BUFSZ 65536
#define OFF_L (2*BUFSZ)
#define SMEM_DYN (2*BUFSZ + 512 + 1024)

__global__ __launch_bounds__(512,1) void attn_hmma(float* __restrict__ out_ext, int stage) {
    extern __shared__ char dsm[];
    uint32_t raw = smem_u32(dsm);
    uint32_t sb  = (raw + 1023) & ~1023u;
    char* bp = dsm + (sb - raw);
    float* sml = (float*)(bp + OFF_L);

    int h = blockIdx.y, i0 = blockIdx.x*128;
    int tid = threadIdx.x, lane = tid & 31, wid = tid >> 5;
    bool producer = (wid >= 8);

    if (producer) {
        int ptid = tid - 256;
        int r = ptid >> 1, jh = ptid & 1;
        float2 efs = g_EFs[h*N_ + i0 + r];
        float Ei = efs.x, Fi = efs.y;
        const float2*   efd    = g_EFd + h*N_;
        const unsigned* adjrow = g_adjb + (size_t)(i0+r)*NW_;
        const char* whh = (const char*)(g_whT_hi + (size_t)h*D_*N_);
        const char* whl = (const char*)(g_whT_lo + (size_t)h*D_*N_);
        float rsum = 0.f;

        auto loadW = [&](uint32_t tb, int c){
            int j0 = c * 64;
            #pragma unroll
            for (int l=0;l<4;l++){
                int idx = ptid + l*256;
                int f = idx >> 3, seg = idx & 7;
                size_t go = (((size_t)f*N_ + j0) << 1) + (size_t)seg*16;
                uint32_t so = SW128((uint32_t)(f*128 + seg*16));
                cpasync16(sb + tb + WB_HI + so, whh + go);
                cpasync16(sb + tb + WB_LO + so, whl + go);
            }
            CP_COMMIT();
        };
        auto genP = [&](uint32_t tb, int c){
            int j0 = c * 64;
            unsigned w = adjrow[(j0>>5) + jh];
            const float4* efp = (const float4*)(efd + j0 + jh*32);
            uint32_t rb = (uint32_t)(r*128 + jh*64);
            #pragma unroll
            for (int q=0;q<16;q++){
                float4 e01 = efp[q];
                float p0 = fmaxf(Ei*e01.x, Fi*e01.y);
                float p1 = fmaxf(Ei*e01.z, Fi*e01.w);
                p0 = ((w>>(2*q  ))&1u) ? p0 : 0.f;
                p1 = ((w>>(2*q+1))&1u) ? p1 : 0.f;
                rsum += p0 + p1;
                float l0, l1;
                uint32_t hb = pack_hi(p0, p1, l0, l1);
                __nv_bfloat162 lp = __floats2bfloat162_rn(l0, l1);
                uint32_t so = SW128(rb + q*4);
                *(uint32_t*)(bp + tb + PB_HI + so) = hb;
                *(uint32_t*)(bp + tb + PB_LO + so) = *(uint32_t*)&lp;
            }
        };

        loadW(0u, 0);
        genP(0u, 0);
        CP_WAIT0();
        __syncthreads();
        for (int c = 0; c < 64; ++c) {
            uint32_t nb = (uint32_t)(~c & 1) * BUFSZ;
            if (c < 63){
                loadW(nb, c+1);          // async first, hidden under genP
                genP(nb, c+1);
                CP_WAIT0();
            }
            __syncthreads();
        }
        float full = rsum + __shfl_xor_sync(0xffffffffu, rsum, 1);
        if (!(ptid & 1)) sml[r] = 1.0f / full;
        __syncthreads();
    } else {
        int wm = wid >> 2, wn = wid & 3;
        float acc[4][4][4];
        #pragma unroll
        for (int a=0;a<4;a++)
            #pragma unroll
            for (int b=0;b<4;b++)
                #pragma unroll
                for (int c=0;c<4;c++) acc[a][b][c]=0.f;

        __syncthreads();
        for (int c = 0; c < 64; ++c) {
            uint32_t tb = (uint32_t)(c & 1) * BUFSZ;
            #pragma unroll
            for (int kt=0;kt<4;kt++){
                uint32_t kb = (uint32_t)(kt*32 + (lane>>4)*16);
                uint32_t bh[4][2], bl[4][2];
                #pragma unroll
                for (int pp=0;pp<2;pp++){
                    uint32_t off = SW128((uint32_t)((wn*32 + pp*16 + (lane&15))*128) + kb);
                    uint32_t t0[4], t1[4];
                    ldsm4(t0, sb + tb + WB_HI + off);
                    ldsm4(t1, sb + tb + WB_LO + off);
                    bh[pp*2  ][0]=t0[0]; bh[pp*2  ][1]=t0[2];
                    bh[pp*2+1][0]=t0[1]; bh[pp*2+1][1]=t0[3];
                    bl[pp*2  ][0]=t1[0]; bl[pp*2  ][1]=t1[2];
                    bl[pp*2+1][0]=t1[1]; bl[pp*2+1][1]=t1[3];
                }
                #pragma unroll
                for (int mt=0;mt<4;mt++){
                    uint32_t off = SW128((uint32_t)((wm*64 + mt*16 + (lane&15))*128) + kb);
                    uint32_t ah[4], al[4];
                    ldsm4(ah, sb + tb + PB_HI + off);
                    ldsm4(al, sb + tb + PB_LO + off);
                    #pragma unroll
                    for (int nt=0;nt<4;nt++){
                        mma16816(acc[mt][nt], ah, bh[nt]);
                        mma16816(acc[mt][nt], ah, bl[nt]);
                        mma16816(acc[mt][nt], al, bh[nt]);
                    }
                }
            }
            __syncthreads();
        }
        __syncthreads();                 // sml ready
        #pragma unroll
        for (int mt=0;mt<4;mt++){
            int r0 = wm*64 + mt*16 + (lane>>2);
            float il0 = sml[r0], il1 = sml[r0+8];
            #pragma unroll
            for (int nt=0;nt<4;nt++){
                int fcol = wn*32 + nt*8 + (lane&3)*2;
                float2 v0, v1;
                v0.x = eluf(acc[mt][nt][0]*il0);
                v0.y = eluf(acc[mt][nt][1]*il0);
                v1.x = eluf(acc[mt][nt][2]*il1);
                v1.y = eluf(acc[mt][nt][3]*il1);
                if (stage == 1){
                    size_t o0 = ((size_t)(i0+r0  )*KX_ + h*D_ + fcol);
                    size_t o1 = ((size_t)(i0+r0+8)*KX_ + h*D_ + fcol);
                    float l0a, l0b, l1a, l1b;
                    uint32_t h0 = pack_hi(v0.x, v0.y, l0a, l0b);
                    uint32_t h1 = pack_hi(v1.x, v1.y, l1a, l1b);
                    __nv_bfloat162 lo0 = __floats2bfloat162_rn(l0a, l0b);
                    __nv_bfloat162 lo1 = __floats2bfloat162_rn(l1a, l1b);
                    *(uint32_t*)((char*)g_x_hi + o0*2) = h0;
                    *(uint32_t*)((char*)g_x_lo + o0*2) = *(uint32_t*)&lo0;
                    *(uint32_t*)((char*)g_x_hi + o1*2) = h1;
                    *(uint32_t*)((char*)g_x_lo + o1*2) = *(uint32_t*)&lo1;
                } else {
                    *(float2*)(out_ext + (size_t)(i0+r0  )*KX_ + h*D_ + fcol) = v0;
                    *(float2*)(out_ext + (size_t)(i0+r0+8)*KX_ + h*D_ + fcol) = v1;
                }
            }
        }
    }
}

// ---------------- launch ----------------
extern "C" void kernel_launch(void* const* d_in, const int* in_sizes, int n_in,
                              void* d_out, int out_size) {
    const float* chems = (const float*)d_in[0];
    const int*   adj   = (const int*)  d_in[1];
    const float* W1    = (const float*)d_in[2];
    const float* a1    = (const float*)d_in[3];
    const float* W2    = (const float*)d_in[4];
    const float* a2    = (const float*)d_in[5];
    float* out = (float*)d_out;

    cudaFuncSetAttribute(attn_hmma, cudaFuncAttributeMaxDynamicSharedMemorySize, SMEM_DYN);
    cudaFuncSetAttribute(gemm_hmma, cudaFuncAttributeMaxDynamicSharedMemorySize, SMEMG);

    pack_adj<<<1024, 256>>>(adj);
    split_ch<<<H_*N_*D_/1024, 256>>>(chems);
    split_WT<<<dim3(4, 4, H_), 256>>>(W1, 128, 1);
    split_WT<<<dim3(16, 4, H_), 256>>>(W2, 512, 2);

    // stage 1
    gemm_hmma<<<dim3(N_/128, H_), 256, SMEMG>>>(1, 128);
    cvt_whT<<<dim3(N_/32, D_/32, H_), 256>>>();
    srcdst_k<<<dim3(N_/8, H_), 256>>>(a1);
    attn_hmma<<<dim3(N_/128, H_), 512, SMEM_DYN>>>(nullptr, 1);

    // stage 2
    gemm_hmma<<<dim3(N_/128, H_), 256, SMEMG>>>(2, 512);
    cvt_whT<<<dim3(N_/32, D_/32, H_), 256>>>();
    srcdst_k<<<dim3(N_/8, H_), 256>>>(a2);
    attn_hmma<<<dim3(N_/128, H_), 512, SMEM_DYN>>>(out, 2);
}

// round 8
// speedup vs baseline: 4.6969x; 1.3204x over previous
#include <cuda_runtime.h>
#include <cuda_bf16.h>
#include <cuda_fp16.h>
#include <cstdint>

#define H_ 4
#define N_ 4096
#define D_ 128
#define KX_ 512            // H * D
#define NW_ (N_/32)        // 128 mask words per row
#define ALPHA_ 0.2f

// ---------------- device scratch (uint4-backed for 16B alignment) --------
__device__ float    g_Wh[H_*N_*D_];          // 8 MB fp32 Wh
__device__ unsigned g_adjb[N_*NW_];          // 2 MB adjacency bitmask
__device__ float2   g_EFs[H_*N_];            // rows: {e^s, e^.2s}
__device__ float2   g_EFd[H_*N_];            // cols: {e^d, e^.2d}
__device__ uint4    g_whT_hi4[H_*D_*N_/8];   // Wh^T hi (fp16) [h][f][j]
__device__ uint4    g_whT_lo4[H_*D_*N_/8];   // Wh^T lo (fp16)
__device__ uint4    g_ch_hi4 [H_*N_*D_/8];   // chems hi/lo (bf16)
__device__ uint4    g_ch_lo4 [H_*N_*D_/8];
__device__ uint4    g_x_hi4  [N_*KX_/8];     // stage-1 output hi/lo (bf16)
__device__ uint4    g_x_lo4  [N_*KX_/8];
__device__ uint4    g_W1T_hi4[H_*D_*D_/8];   // W1^T (bf16) [h][dout][k]
__device__ uint4    g_W1T_lo4[H_*D_*D_/8];
__device__ uint4    g_W2T_hi4[H_*D_*KX_/8];  // W2^T (bf16) [h][dout][k]
__device__ uint4    g_W2T_lo4[H_*D_*KX_/8];

// device-code-only views (NEVER pass these as kernel args from host!)
#define g_whT_hi ((__half*)g_whT_hi4)
#define g_whT_lo ((__half*)g_whT_lo4)
#define g_ch_hi  ((__nv_bfloat16*)g_ch_hi4)
#define g_ch_lo  ((__nv_bfloat16*)g_ch_lo4)
#define g_x_hi   ((__nv_bfloat16*)g_x_hi4)
#define g_x_lo   ((__nv_bfloat16*)g_x_lo4)
#define g_W1T_hi ((__nv_bfloat16*)g_W1T_hi4)
#define g_W1T_lo ((__nv_bfloat16*)g_W1T_lo4)
#define g_W2T_hi ((__nv_bfloat16*)g_W2T_hi4)
#define g_W2T_lo ((__nv_bfloat16*)g_W2T_lo4)

// ---------------- helpers ----------------
__device__ __forceinline__ uint32_t smem_u32(const void* p){
    uint32_t a;
    asm("{ .reg .u64 t; cvta.to.shared.u64 t, %1; cvt.u32.u64 %0, t; }"
        : "=r"(a) : "l"(p));
    return a;
}
#define SW128(o) ((o) ^ (((o) >> 3) & 0x70))

__device__ __forceinline__ float eluf(float x){ return x > 0.f ? x : expm1f(x); }

__device__ __forceinline__ float fexp(float x){
    const float L2E   = 1.4426950408889634f;
    const float MAGIC = 12582912.0f;
    float t  = x * L2E;
    float kf = t + MAGIC;
    int   ki = __float_as_int(kf);
    float km = kf - MAGIC;
    float f  = t - km;
    float p  = 1.33335581e-3f;
    p = fmaf(p, f, 9.61812910e-3f);
    p = fmaf(p, f, 5.55041087e-2f);
    p = fmaf(p, f, 2.40226507e-1f);
    p = fmaf(p, f, 6.93147180e-1f);
    p = fmaf(p, f, 1.0f);
    return __int_as_float(__float_as_int(p) + (int)((unsigned)ki << 23));
}

__device__ __forceinline__ void ldsm4(uint32_t* r, uint32_t addr){
    asm volatile("ldmatrix.sync.aligned.m8n8.x4.shared.b16 {%0,%1,%2,%3}, [%4];"
        : "=r"(r[0]),"=r"(r[1]),"=r"(r[2]),"=r"(r[3]) : "r"(addr));
}
__device__ __forceinline__ void mma16816(float* c, const uint32_t* a, const uint32_t* b){
    asm volatile("mma.sync.aligned.m16n8k16.row.col.f32.bf16.bf16.f32 "
        "{%0,%1,%2,%3}, {%4,%5,%6,%7}, {%8,%9}, {%0,%1,%2,%3};"
        : "+f"(c[0]),"+f"(c[1]),"+f"(c[2]),"+f"(c[3])
        : "r"(a[0]),"r"(a[1]),"r"(a[2]),"r"(a[3]), "r"(b[0]),"r"(b[1]));
}
__device__ __forceinline__ void mma16816h(float* c, const uint32_t* a, const uint32_t* b){
    asm volatile("mma.sync.aligned.m16n8k16.row.col.f32.f16.f16.f32 "
        "{%0,%1,%2,%3}, {%4,%5,%6,%7}, {%8,%9}, {%0,%1,%2,%3};"
        : "+f"(c[0]),"+f"(c[1]),"+f"(c[2]),"+f"(c[3])
        : "r"(a[0]),"r"(a[1]),"r"(a[2]),"r"(a[3]), "r"(b[0]),"r"(b[1]));
}
__device__ __forceinline__ void cpasync16(uint32_t dst, const void* src){
    asm volatile("cp.async.cg.shared.global [%0], [%1], 16;" :: "r"(dst), "l"(src));
}
#define CP_COMMIT() asm volatile("cp.async.commit_group;" ::: "memory")
#define CP_WAIT0()  asm volatile("cp.async.wait_group 0;"  ::: "memory")

__device__ __forceinline__ uint32_t pack_hi(float a, float b, float& ra, float& rb){
    __nv_bfloat162 hp = __floats2bfloat162_rn(a, b);
    uint32_t hb = *(uint32_t*)&hp;
    ra = a - __uint_as_float(hb << 16);
    rb = b - __uint_as_float(hb & 0xffff0000u);
    return hb;
}

// ---------------- K0: pack adj ----------------
__global__ void pack_adj(const int* __restrict__ adj) {
    int gwarp  = (blockIdx.x*blockDim.x + threadIdx.x) >> 5;
    int lane   = threadIdx.x & 31;
    int nwarps = (gridDim.x*blockDim.x) >> 5;
    for (int w = gwarp; w < N_*NW_; w += nwarps) {
        int v = adj[(size_t)w*32 + lane];
        unsigned bits = __ballot_sync(0xffffffffu, v > 0);
        if (lane == 0) g_adjb[w] = bits;
    }
}

// ---------------- K0b: split chems -> bf16 hi/lo ----------------
__global__ void split_ch(const float* __restrict__ c){
    size_t i = ((size_t)blockIdx.x*blockDim.x + threadIdx.x)*4;
    float4 v = *(const float4*)(c + i);
    float rx,ry,rz,rw;
    uint32_t h0 = pack_hi(v.x, v.y, rx, ry);
    uint32_t h1 = pack_hi(v.z, v.w, rz, rw);
    __nv_bfloat162 l0 = __floats2bfloat162_rn(rx, ry);
    __nv_bfloat162 l1 = __floats2bfloat162_rn(rz, rw);
    uint2 ho = make_uint2(h0, h1);
    uint2 lo = make_uint2(*(uint32_t*)&l0, *(uint32_t*)&l1);
    *(uint2*)((char*)g_ch_hi + i*2) = ho;
    *(uint2*)((char*)g_ch_lo + i*2) = lo;
}

// ---------------- K0c: W [h][K][128] -> W^T hi/lo [h][128][K] ----------
__global__ void split_WT(const float* __restrict__ W, int K, int which){
    __shared__ float ts[32][33];
    __nv_bfloat16* Thi = (which==1) ? g_W1T_hi : g_W2T_hi;
    __nv_bfloat16* Tlo = (which==1) ? g_W1T_lo : g_W2T_lo;
    int h = blockIdx.z, k0 = blockIdx.x*32, f0 = blockIdx.y*32;
    int tx = threadIdx.x & 31, ty = threadIdx.x >> 5;
    const float* Wh = W + (size_t)h*K*128;
    #pragma unroll
    for (int r=0;r<4;r++)
        ts[ty + r*8][tx] = Wh[(size_t)(k0 + ty + r*8)*128 + f0 + tx];
    __syncthreads();
    #pragma unroll
    for (int r=0;r<4;r++){
        int f = f0 + ty + r*8;
        float v = ts[tx][ty + r*8];
        __nv_bfloat16 hi = __float2bfloat16(v);
        __nv_bfloat16 lo = __float2bfloat16(v - __bfloat162float(hi));
        size_t o = ((size_t)h*128 + f)*K + k0 + tx;
        Thi[o] = hi; Tlo[o] = lo;
    }
}

// ---------------- K1: Wh = X @ W via 3-term bf16 HMMA -------------------
#define GA_HI 0
#define GA_LO 32768
#define GB_HI 65536
#define GB_LO 98304
#define SMEMG (131072 + 1024)

__global__ __launch_bounds__(256,1) void gemm_hmma(int stage, int K)
{
    extern __shared__ char dsm[];
    uint32_t raw = smem_u32(dsm);
    uint32_t sb  = (raw + 1023) & ~1023u;

    const __nv_bfloat16 *Ahi, *Alo, *BThi, *BTlo;
    long aHeadStride;
    if (stage == 1){
        Ahi = g_ch_hi; Alo = g_ch_lo;
        BThi = g_W1T_hi; BTlo = g_W1T_lo;
        aHeadStride = (long)N_*D_;
    } else {
        Ahi = g_x_hi; Alo = g_x_lo;
        BThi = g_W2T_hi; BTlo = g_W2T_lo;
        aHeadStride = 0;
    }

    int h = blockIdx.y, m0 = blockIdx.x*128;
    int tid = threadIdx.x, lane = tid & 31, wid = tid >> 5;
    int wm = wid >> 2, wn = wid & 3;
    const char* pAhi = (const char*)(Ahi + (size_t)h*aHeadStride + (size_t)m0*K);
    const char* pAlo = (const char*)(Alo + (size_t)h*aHeadStride + (size_t)m0*K);
    const char* pBhi = (const char*)(BThi + (size_t)h*128*K);
    const char* pBlo = (const char*)(BTlo + (size_t)h*128*K);
    long rs = (long)K*2;

    float acc[4][4][4];
    #pragma unroll
    for (int a=0;a<4;a++)
        #pragma unroll
        for (int b=0;b<4;b++)
            #pragma unroll
            for (int c=0;c<4;c++) acc[a][b][c]=0.f;

    auto ldpart = [&](uint32_t dstBase, const char* g, long colByte){
        #pragma unroll
        for (int l=0;l<8;l++){
            int idx = tid + l*256;
            int row = idx >> 4;
            int s16 = idx & 15;
            uint32_t so = SW128((uint32_t)(row*128 + (s16&7)*16)) + (uint32_t)(s16>>3)*16384;
            cpasync16(sb + dstBase + so, g + (long)row*rs + colByte + s16*16);
        }
    };

    int nk = K >> 7;
    for (int kc = 0; kc < nk; ++kc){
        long cb = (long)kc*256;
        ldpart(GA_HI, pAhi, cb);
        ldpart(GA_LO, pAlo, cb);
        ldpart(GB_HI, pBhi, cb);
        ldpart(GB_LO, pBlo, cb);
        CP_COMMIT();
        CP_WAIT0();
        __syncthreads();
        #pragma unroll
        for (int kt=0;kt<8;kt++){
            uint32_t subo = (uint32_t)(kt>>2)*16384;
            uint32_t kb = (uint32_t)((kt&3)*32 + (lane>>4)*16);
            uint32_t bh[4][2], bl[4][2];
            #pragma unroll
            for (int pp=0;pp<2;pp++){
                uint32_t off = SW128((uint32_t)((wn*32 + pp*16 + (lane&15))*128) + kb) + subo;
                uint32_t t0[4], t1[4];
                ldsm4(t0, sb + GB_HI + off);
                ldsm4(t1, sb + GB_LO + off);
                bh[pp*2  ][0]=t0[0]; bh[pp*2  ][1]=t0[2];
                bh[pp*2+1][0]=t0[1]; bh[pp*2+1][1]=t0[3];
                bl[pp*2  ][0]=t1[0]; bl[pp*2  ][1]=t1[2];
                bl[pp*2+1][0]=t1[1]; bl[pp*2+1][1]=t1[3];
            }
            #pragma unroll
            for (int mt=0;mt<4;mt++){
                uint32_t off = SW128((uint32_t)((wm*64 + mt*16 + (lane&15))*128) + kb) + subo;
                uint32_t ah[4], al[4];
                ldsm4(ah, sb + GA_HI + off);
                ldsm4(al, sb + GA_LO + off);
                #pragma unroll
                for (int nt=0;nt<4;nt++){
                    mma16816(acc[mt][nt], ah, bh[nt]);
                    mma16816(acc[mt][nt], ah, bl[nt]);
                    mma16816(acc[mt][nt], al, bh[nt]);
                }
            }
        }
        __syncthreads();
    }
    float* Ch = g_Wh + (size_t)h*N_*D_;
    #pragma unroll
    for (int mt=0;mt<4;mt++){
        int r0 = m0 + wm*64 + mt*16 + (lane>>2);
        #pragma unroll
        for (int nt=0;nt<4;nt++){
            int fcol = wn*32 + nt*8 + (lane&3)*2;
            *(float2*)(Ch + (size_t)r0*D_ + fcol)     = make_float2(acc[mt][nt][0], acc[mt][nt][1]);
            *(float2*)(Ch + (size_t)(r0+8)*D_ + fcol) = make_float2(acc[mt][nt][2], acc[mt][nt][3]);
        }
    }
}

// ---------------- K1b: Wh^T -> fp16 hi/lo ----------------
__global__ __launch_bounds__(256) void cvt_whT() {
    __shared__ float ts[32][33];
    int h  = blockIdx.z;
    int j0 = blockIdx.x * 32;
    int f0 = blockIdx.y * 32;
    int tx = threadIdx.x & 31, ty = threadIdx.x >> 5;
    const float* Wh = g_Wh + (size_t)h*N_*D_;
    #pragma unroll
    for (int r=0;r<4;r++){
        int j = j0 + ty + r*8;
        ts[ty + r*8][tx] = Wh[(size_t)j*D_ + f0 + tx];
    }
    __syncthreads();
    #pragma unroll
    for (int r=0;r<4;r++){
        int f = f0 + ty + r*8;
        float v = ts[tx][ty + r*8];
        __half hi = __float2half_rn(v);
        __half lo = __float2half_rn(v - __half2float(hi));
        size_t o = ((size_t)(h*D_ + f))*N_ + j0 + tx;
        g_whT_hi[o] = hi;
        g_whT_lo[o] = lo;
    }
}

// ---------------- K2: src/dst dots -> per-node exp factors ---------------
__global__ void srcdst_k(const float* __restrict__ avec) {
    int h = blockIdx.y;
    int warp = threadIdx.x >> 5, lane = threadIdx.x & 31;
    int i = blockIdx.x*8 + warp;
    const float* wh = g_Wh + ((size_t)h*N_ + i)*D_;
    const float* av = avec + h*2*D_;
    float4 w4 = *(const float4*)&wh[lane*4];
    float4 s4 = *(const float4*)&av[lane*4];
    float4 d4 = *(const float4*)&av[D_ + lane*4];
    float s = w4.x*s4.x + w4.y*s4.y + w4.z*s4.z + w4.w*s4.w;
    float d = w4.x*d4.x + w4.y*d4.y + w4.z*d4.z + w4.w*d4.w;
    #pragma unroll
    for (int o=16;o>0;o>>=1){
        s += __shfl_down_sync(0xffffffffu, s, o);
        d += __shfl_down_sync(0xffffffffu, d, o);
    }
    if (lane==0){
        g_EFs[h*N_+i] = make_float2(fexp(s), fexp(ALPHA_*s));
        g_EFd[h*N_+i] = make_float2(fexp(d), fexp(ALPHA_*d));
    }
}

// ---------------- K3: warp-specialized attn, fp16 2-term ------------------
// P single fp16 tile; W fp16 hi/lo. 2 MMAs per (mt,nt,kt).
#define PB    0
#define WB_HI 16384
#define WB_LO 32768
#define BUFSZ 49152
#define OFF_L (2*BUFSZ)
#define SMEM_DYN (2*BUFSZ + 512 + 1024)

__global__ __launch_bounds__(512,1) void attn_hmma(float* __restrict__ out_ext, int stage) {
    extern __shared__ char dsm[];
    uint32_t raw = smem_u32(dsm);
    uint32_t sb  = (raw + 1023) & ~1023u;
    char* bp = dsm + (sb - raw);
    float* sml = (float*)(bp + OFF_L);

    int h = blockIdx.y, i0 = blockIdx.x*128;
    int tid = threadIdx.x, lane = tid & 31, wid = tid >> 5;
    bool producer = (wid >= 8);

    if (producer) {
        int ptid = tid - 256;
        int r = ptid >> 1, jh = ptid & 1;
        float2 efs = g_EFs[h*N_ + i0 + r];
        float Ei = efs.x, Fi = efs.y;
        const float2*   efd    = g_EFd + h*N_;
        const unsigned* adjrow = g_adjb + (size_t)(i0+r)*NW_;
        const char* whh = (const char*)(g_whT_hi + (size_t)h*D_*N_);
        const char* whl = (const char*)(g_whT_lo + (size_t)h*D_*N_);
        float rsum = 0.f;

        auto loadW = [&](uint32_t tb, int c){
            int j0 = c * 64;
            #pragma unroll
            for (int l=0;l<4;l++){
                int idx = ptid + l*256;
                int f = idx >> 3, seg = idx & 7;
                size_t go = (((size_t)f*N_ + j0) << 1) + (size_t)seg*16;
                uint32_t so = SW128((uint32_t)(f*128 + seg*16));
                cpasync16(sb + tb + WB_HI + so, whh + go);
                cpasync16(sb + tb + WB_LO + so, whl + go);
            }
            CP_COMMIT();
        };
        auto genP = [&](uint32_t tb, int c){
            int j0 = c * 64;
            unsigned w = adjrow[(j0>>5) + jh];
            const float4* efp = (const float4*)(efd + j0 + jh*32);
            uint32_t rb = (uint32_t)(r*128 + jh*64);
            #pragma unroll
            for (int q=0;q<16;q++){
                float4 e01 = efp[q];
                float p0 = fmaxf(Ei*e01.x, Fi*e01.y);
                float p1 = fmaxf(Ei*e01.z, Fi*e01.w);
                p0 = ((w>>(2*q  ))&1u) ? p0 : 0.f;
                p1 = ((w>>(2*q+1))&1u) ? p1 : 0.f;
                rsum += p0 + p1;
                __half2 hp = __floats2half2_rn(p0, p1);
                *(uint32_t*)(bp + tb + PB + SW128(rb + q*4)) = *(uint32_t*)&hp;
            }
        };

        loadW(0u, 0);
        genP(0u, 0);
        CP_WAIT0();
        __syncthreads();
        for (int c = 0; c < 64; ++c) {
            uint32_t nb = (uint32_t)(~c & 1) * BUFSZ;
            if (c < 63){
                loadW(nb, c+1);          // async first, hidden under genP
                genP(nb, c+1);
                CP_WAIT0();
            }
            __syncthreads();
        }
        float full = rsum + __shfl_xor_sync(0xffffffffu, rsum, 1);
        if (!(ptid & 1)) sml[r] = 1.0f / full;
        __syncthreads();
    } else {
        int wm = wid >> 2, wn = wid & 3;
        float acc[4][4][4];
        #pragma unroll
        for (int a=0;a<4;a++)
            #pragma unroll
            for (int b=0;b<4;b++)
                #pragma unroll
                for (int c=0;c<4;c++) acc[a][b][c]=0.f;

        __syncthreads();
        for (int c = 0; c < 64; ++c) {
            uint32_t tb = (uint32_t)(c & 1) * BUFSZ;
            #pragma unroll
            for (int kt=0;kt<4;kt++){
                uint32_t kb = (uint32_t)(kt*32 + (lane>>4)*16);
                uint32_t bh[4][2], bl[4][2];
                #pragma unroll
                for (int pp=0;pp<2;pp++){
                    uint32_t off = SW128((uint32_t)((wn*32 + pp*16 + (lane&15))*128) + kb);
                    uint32_t t0[4], t1[4];
                    ldsm4(t0, sb + tb + WB_HI + off);
                    ldsm4(t1, sb + tb + WB_LO + off);
                    bh[pp*2  ][0]=t0[0]; bh[pp*2  ][1]=t0[2];
                    bh[pp*2+1][0]=t0[1]; bh[pp*2+1][1]=t0[3];
                    bl[pp*2  ][0]=t1[0]; bl[pp*2  ][1]=t1[2];
                    bl[pp*2+1][0]=t1[1]; bl[pp*2+1][1]=t1[3];
                }
                #pragma unroll
                for (int mt=0;mt<4;mt++){
                    uint32_t off = SW128((uint32_t)((wm*64 + mt*16 + (lane&15))*128) + kb);
                    uint32_t ah[4];
                    ldsm4(ah, sb + tb + PB + off);
                    #pragma unroll
                    for (int nt=0;nt<4;nt++){
                        mma16816h(acc[mt][nt], ah, bh[nt]);
                        mma16816h(acc[mt][nt], ah, bl[nt]);
                    }
                }
            }
            __syncthreads();
        }
        __syncthreads();                 // sml ready
        #pragma unroll
        for (int mt=0;mt<4;mt++){
            int r0 = wm*64 + mt*16 + (lane>>2);
            float il0 = sml[r0], il1 = sml[r0+8];
            #pragma unroll
            for (int nt=0;nt<4;nt++){
                int fcol = wn*32 + nt*8 + (lane&3)*2;
                float2 v0, v1;
                v0.x = eluf(acc[mt][nt][0]*il0);
                v0.y = eluf(acc[mt][nt][1]*il0);
                v1.x = eluf(acc[mt][nt][2]*il1);
                v1.y = eluf(acc[mt][nt][3]*il1);
                if (stage == 1){
                    size_t o0 = ((size_t)(i0+r0  )*KX_ + h*D_ + fcol);
                    size_t o1 = ((size_t)(i0+r0+8)*KX_ + h*D_ + fcol);
                    float l0a, l0b, l1a, l1b;
                    uint32_t h0 = pack_hi(v0.x, v0.y, l0a, l0b);
                    uint32_t h1 = pack_hi(v1.x, v1.y, l1a, l1b);
                    __nv_bfloat162 lo0 = __floats2bfloat162_rn(l0a, l0b);
                    __nv_bfloat162 lo1 = __floats2bfloat162_rn(l1a, l1b);
                    *(uint32_t*)((char*)g_x_hi + o0*2) = h0;
                    *(uint32_t*)((char*)g_x_lo + o0*2) = *(uint32_t*)&lo0;
                    *(uint32_t*)((char*)g_x_hi + o1*2) = h1;
                    *(uint32_t*)((char*)g_x_lo + o1*2) = *(uint32_t*)&lo1;
                } else {
                    *(float2*)(out_ext + (size_t)(i0+r0  )*KX_ + h*D_ + fcol) = v0;
                    *(float2*)(out_ext + (size_t)(i0+r0+8)*KX_ + h*D_ + fcol) = v1;
                }
            }
        }
    }
}

// ---------------- launch ----------------
extern "C" void kernel_launch(void* const* d_in, const int* in_sizes, int n_in,
                              void* d_out, int out_size) {
    const float* chems = (const float*)d_in[0];
    const int*   adj   = (const int*)  d_in[1];
    const float* W1    = (const float*)d_in[2];
    const float* a1    = (const float*)d_in[3];
    const float* W2    = (const float*)d_in[4];
    const float* a2    = (const float*)d_in[5];
    float* out = (float*)d_out;

    cudaFuncSetAttribute(attn_hmma, cudaFuncAttributeMaxDynamicSharedMemorySize, SMEM_DYN);
    cudaFuncSetAttribute(gemm_hmma, cudaFuncAttributeMaxDynamicSharedMemorySize, SMEMG);

    pack_adj<<<1024, 256>>>(adj);
    split_ch<<<H_*N_*D_/1024, 256>>>(chems);
    split_WT<<<dim3(4, 4, H_), 256>>>(W1, 128, 1);
    split_WT<<<dim3(16, 4, H_), 256>>>(W2, 512, 2);

    // stage 1
    gemm_hmma<<<dim3(N_/128, H_), 256, SMEMG>>>(1, 128);
    cvt_whT<<<dim3(N_/32, D_/32, H_), 256>>>();
    srcdst_k<<<dim3(N_/8, H_), 256>>>(a1);
    attn_hmma<<<dim3(N_/128, H_), 512, SMEM_DYN>>>(nullptr, 1);

    // stage 2
    gemm_hmma<<<dim3(N_/128, H_), 256, SMEMG>>>(2, 512);
    cvt_whT<<<dim3(N_/32, D_/32, H_), 256>>>();
    srcdst_k<<<dim3(N_/8, H_), 256>>>(a2);
    attn_hmma<<<dim3(N_/128, H_), 512, SMEM_DYN>>>(out, 2);
}

// round 9
// speedup vs baseline: 5.8479x; 1.2451x over previous
#include <cuda_runtime.h>
#include <cuda_bf16.h>
#include <cuda_fp16.h>
#include <cstdint>

#define H_ 4
#define N_ 4096
#define D_ 128
#define KX_ 512            // H * D
#define NW_ (N_/32)        // 128 mask words per row
#define ALPHA_ 0.2f

// ---------------- device scratch (uint4-backed for 16B alignment) --------
__device__ float    g_Wh[H_*N_*D_];          // 8 MB fp32 Wh
__device__ unsigned g_adjb[N_*NW_];          // 2 MB adjacency bitmask
__device__ float2   g_EFs[H_*N_];            // rows: {e^s, e^.2s}
__device__ float2   g_EFd[H_*N_];            // cols: {e^d, e^.2d}
__device__ uint4    g_whT_hi4[H_*D_*N_/8];   // Wh^T (fp16) [h][f][j]
__device__ uint4    g_ch_hi4 [H_*N_*D_/8];   // chems hi/lo (bf16)
__device__ uint4    g_ch_lo4 [H_*N_*D_/8];
__device__ uint4    g_x_hi4  [N_*KX_/8];     // stage-1 output hi/lo (bf16)
__device__ uint4    g_x_lo4  [N_*KX_/8];
__device__ uint4    g_W1T_hi4[H_*D_*D_/8];   // W1^T (bf16) [h][dout][k]
__device__ uint4    g_W1T_lo4[H_*D_*D_/8];
__device__ uint4    g_W2T_hi4[H_*D_*KX_/8];  // W2^T (bf16) [h][dout][k]
__device__ uint4    g_W2T_lo4[H_*D_*KX_/8];

// device-code-only views (NEVER pass these as kernel args from host!)
#define g_whT_hi ((__half*)g_whT_hi4)
#define g_ch_hi  ((__nv_bfloat16*)g_ch_hi4)
#define g_ch_lo  ((__nv_bfloat16*)g_ch_lo4)
#define g_x_hi   ((__nv_bfloat16*)g_x_hi4)
#define g_x_lo   ((__nv_bfloat16*)g_x_lo4)
#define g_W1T_hi ((__nv_bfloat16*)g_W1T_hi4)
#define g_W1T_lo ((__nv_bfloat16*)g_W1T_lo4)
#define g_W2T_hi ((__nv_bfloat16*)g_W2T_hi4)
#define g_W2T_lo ((__nv_bfloat16*)g_W2T_lo4)

// ---------------- helpers ----------------
__device__ __forceinline__ uint32_t smem_u32(const void* p){
    uint32_t a;
    asm("{ .reg .u64 t; cvta.to.shared.u64 t, %1; cvt.u32.u64 %0, t; }"
        : "=r"(a) : "l"(p));
    return a;
}
#define SW128(o) ((o) ^ (((o) >> 3) & 0x70))

__device__ __forceinline__ float eluf(float x){ return x > 0.f ? x : expm1f(x); }

__device__ __forceinline__ float fexp(float x){
    const float L2E   = 1.4426950408889634f;
    const float MAGIC = 12582912.0f;
    float t  = x * L2E;
    float kf = t + MAGIC;
    int   ki = __float_as_int(kf);
    float km = kf - MAGIC;
    float f  = t - km;
    float p  = 1.33335581e-3f;
    p = fmaf(p, f, 9.61812910e-3f);
    p = fmaf(p, f, 5.55041087e-2f);
    p = fmaf(p, f, 2.40226507e-1f);
    p = fmaf(p, f, 6.93147180e-1f);
    p = fmaf(p, f, 1.0f);
    return __int_as_float(__float_as_int(p) + (int)((unsigned)ki << 23));
}

__device__ __forceinline__ void ldsm4(uint32_t* r, uint32_t addr){
    asm volatile("ldmatrix.sync.aligned.m8n8.x4.shared.b16 {%0,%1,%2,%3}, [%4];"
        : "=r"(r[0]),"=r"(r[1]),"=r"(r[2]),"=r"(r[3]) : "r"(addr));
}
__device__ __forceinline__ void mma16816(float* c, const uint32_t* a, const uint32_t* b){
    asm volatile("mma.sync.aligned.m16n8k16.row.col.f32.bf16.bf16.f32 "
        "{%0,%1,%2,%3}, {%4,%5,%6,%7}, {%8,%9}, {%0,%1,%2,%3};"
        : "+f"(c[0]),"+f"(c[1]),"+f"(c[2]),"+f"(c[3])
        : "r"(a[0]),"r"(a[1]),"r"(a[2]),"r"(a[3]), "r"(b[0]),"r"(b[1]));
}
__device__ __forceinline__ void mma16816h(float* c, const uint32_t* a, const uint32_t* b){
    asm volatile("mma.sync.aligned.m16n8k16.row.col.f32.f16.f16.f32 "
        "{%0,%1,%2,%3}, {%4,%5,%6,%7}, {%8,%9}, {%0,%1,%2,%3};"
        : "+f"(c[0]),"+f"(c[1]),"+f"(c[2]),"+f"(c[3])
        : "r"(a[0]),"r"(a[1]),"r"(a[2]),"r"(a[3]), "r"(b[0]),"r"(b[1]));
}
__device__ __forceinline__ void cpasync16(uint32_t dst, const void* src){
    asm volatile("cp.async.cg.shared.global [%0], [%1], 16;" :: "r"(dst), "l"(src));
}
#define CP_COMMIT() asm volatile("cp.async.commit_group;" ::: "memory")
#define CP_WAIT0()  asm volatile("cp.async.wait_group 0;"  ::: "memory")

__device__ __forceinline__ uint32_t pack_hi(float a, float b, float& ra, float& rb){
    __nv_bfloat162 hp = __floats2bfloat162_rn(a, b);
    uint32_t hb = *(uint32_t*)&hp;
    ra = a - __uint_as_float(hb << 16);
    rb = b - __uint_as_float(hb & 0xffff0000u);
    return hb;
}

// ---------------- K0: pack adj ----------------
__global__ void pack_adj(const int* __restrict__ adj) {
    int gwarp  = (blockIdx.x*blockDim.x + threadIdx.x) >> 5;
    int lane   = threadIdx.x & 31;
    int nwarps = (gridDim.x*blockDim.x) >> 5;
    for (int w = gwarp; w < N_*NW_; w += nwarps) {
        int v = adj[(size_t)w*32 + lane];
        unsigned bits = __ballot_sync(0xffffffffu, v > 0);
        if (lane == 0) g_adjb[w] = bits;
    }
}

// ---------------- K0b: split chems -> bf16 hi/lo ----------------
__global__ void split_ch(const float* __restrict__ c){
    size_t i = ((size_t)blockIdx.x*blockDim.x + threadIdx.x)*4;
    float4 v = *(const float4*)(c + i);
    float rx,ry,rz,rw;
    uint32_t h0 = pack_hi(v.x, v.y, rx, ry);
    uint32_t h1 = pack_hi(v.z, v.w, rz, rw);
    __nv_bfloat162 l0 = __floats2bfloat162_rn(rx, ry);
    __nv_bfloat162 l1 = __floats2bfloat162_rn(rz, rw);
    uint2 ho = make_uint2(h0, h1);
    uint2 lo = make_uint2(*(uint32_t*)&l0, *(uint32_t*)&l1);
    *(uint2*)((char*)g_ch_hi + i*2) = ho;
    *(uint2*)((char*)g_ch_lo + i*2) = lo;
}

// ---------------- K0c: W [h][K][128] -> W^T hi/lo [h][128][K] ----------
__global__ void split_WT(const float* __restrict__ W, int K, int which){
    __shared__ float ts[32][33];
    __nv_bfloat16* Thi = (which==1) ? g_W1T_hi : g_W2T_hi;
    __nv_bfloat16* Tlo = (which==1) ? g_W1T_lo : g_W2T_lo;
    int h = blockIdx.z, k0 = blockIdx.x*32, f0 = blockIdx.y*32;
    int tx = threadIdx.x & 31, ty = threadIdx.x >> 5;
    const float* Wh = W + (size_t)h*K*128;
    #pragma unroll
    for (int r=0;r<4;r++)
        ts[ty + r*8][tx] = Wh[(size_t)(k0 + ty + r*8)*128 + f0 + tx];
    __syncthreads();
    #pragma unroll
    for (int r=0;r<4;r++){
        int f = f0 + ty + r*8;
        float v = ts[tx][ty + r*8];
        __nv_bfloat16 hi = __float2bfloat16(v);
        __nv_bfloat16 lo = __float2bfloat16(v - __bfloat162float(hi));
        size_t o = ((size_t)h*128 + f)*K + k0 + tx;
        Thi[o] = hi; Tlo[o] = lo;
    }
}

// ---------------- K1: Wh = X @ W via 3-term bf16 HMMA -------------------
#define GA_HI 0
#define GA_LO 32768
#define GB_HI 65536
#define GB_LO 98304
#define SMEMG (131072 + 1024)

__global__ __launch_bounds__(256,1) void gemm_hmma(int stage, int K)
{
    extern __shared__ char dsm[];
    uint32_t raw = smem_u32(dsm);
    uint32_t sb  = (raw + 1023) & ~1023u;

    const __nv_bfloat16 *Ahi, *Alo, *BThi, *BTlo;
    long aHeadStride;
    if (stage == 1){
        Ahi = g_ch_hi; Alo = g_ch_lo;
        BThi = g_W1T_hi; BTlo = g_W1T_lo;
        aHeadStride = (long)N_*D_;
    } else {
        Ahi = g_x_hi; Alo = g_x_lo;
        BThi = g_W2T_hi; BTlo = g_W2T_lo;
        aHeadStride = 0;
    }

    int h = blockIdx.y, m0 = blockIdx.x*128;
    int tid = threadIdx.x, lane = tid & 31, wid = tid >> 5;
    int wm = wid >> 2, wn = wid & 3;
    const char* pAhi = (const char*)(Ahi + (size_t)h*aHeadStride + (size_t)m0*K);
    const char* pAlo = (const char*)(Alo + (size_t)h*aHeadStride + (size_t)m0*K);
    const char* pBhi = (const char*)(BThi + (size_t)h*128*K);
    const char* pBlo = (const char*)(BTlo + (size_t)h*128*K);
    long rs = (long)K*2;

    float acc[4][4][4];
    #pragma unroll
    for (int a=0;a<4;a++)
        #pragma unroll
        for (int b=0;b<4;b++)
            #pragma unroll
            for (int c=0;c<4;c++) acc[a][b][c]=0.f;

    auto ldpart = [&](uint32_t dstBase, const char* g, long colByte){
        #pragma unroll
        for (int l=0;l<8;l++){
            int idx = tid + l*256;
            int row = idx >> 4;
            int s16 = idx & 15;
            uint32_t so = SW128((uint32_t)(row*128 + (s16&7)*16)) + (uint32_t)(s16>>3)*16384;
            cpasync16(sb + dstBase + so, g + (long)row*rs + colByte + s16*16);
        }
    };

    int nk = K >> 7;
    for (int kc = 0; kc < nk; ++kc){
        long cb = (long)kc*256;
        ldpart(GA_HI, pAhi, cb);
        ldpart(GA_LO, pAlo, cb);
        ldpart(GB_HI, pBhi, cb);
        ldpart(GB_LO, pBlo, cb);
        CP_COMMIT();
        CP_WAIT0();
        __syncthreads();
        #pragma unroll
        for (int kt=0;kt<8;kt++){
            uint32_t subo = (uint32_t)(kt>>2)*16384;
            uint32_t kb = (uint32_t)((kt&3)*32 + (lane>>4)*16);
            uint32_t bh[4][2], bl[4][2];
            #pragma unroll
            for (int pp=0;pp<2;pp++){
                uint32_t off = SW128((uint32_t)((wn*32 + pp*16 + (lane&15))*128) + kb) + subo;
                uint32_t t0[4], t1[4];
                ldsm4(t0, sb + GB_HI + off);
                ldsm4(t1, sb + GB_LO + off);
                bh[pp*2  ][0]=t0[0]; bh[pp*2  ][1]=t0[2];
                bh[pp*2+1][0]=t0[1]; bh[pp*2+1][1]=t0[3];
                bl[pp*2  ][0]=t1[0]; bl[pp*2  ][1]=t1[2];
                bl[pp*2+1][0]=t1[1]; bl[pp*2+1][1]=t1[3];
            }
            #pragma unroll
            for (int mt=0;mt<4;mt++){
                uint32_t off = SW128((uint32_t)((wm*64 + mt*16 + (lane&15))*128) + kb) + subo;
                uint32_t ah[4], al[4];
                ldsm4(ah, sb + GA_HI + off);
                ldsm4(al, sb + GA_LO + off);
                #pragma unroll
                for (int nt=0;nt<4;nt++){
                    mma16816(acc[mt][nt], ah, bh[nt]);
                    mma16816(acc[mt][nt], ah, bl[nt]);
                    mma16816(acc[mt][nt], al, bh[nt]);
                }
            }
        }
        __syncthreads();
    }
    float* Ch = g_Wh + (size_t)h*N_*D_;
    #pragma unroll
    for (int mt=0;mt<4;mt++){
        int r0 = m0 + wm*64 + mt*16 + (lane>>2);
        #pragma unroll
        for (int nt=0;nt<4;nt++){
            int fcol = wn*32 + nt*8 + (lane&3)*2;
            *(float2*)(Ch + (size_t)r0*D_ + fcol)     = make_float2(acc[mt][nt][0], acc[mt][nt][1]);
            *(float2*)(Ch + (size_t)(r0+8)*D_ + fcol) = make_float2(acc[mt][nt][2], acc[mt][nt][3]);
        }
    }
}

// ---------------- K1b: Wh^T -> fp16 ----------------
__global__ __launch_bounds__(256) void cvt_whT() {
    __shared__ float ts[32][33];
    int h  = blockIdx.z;
    int j0 = blockIdx.x * 32;
    int f0 = blockIdx.y * 32;
    int tx = threadIdx.x & 31, ty = threadIdx.x >> 5;
    const float* Wh = g_Wh + (size_t)h*N_*D_;
    #pragma unroll
    for (int r=0;r<4;r++){
        int j = j0 + ty + r*8;
        ts[ty + r*8][tx] = Wh[(size_t)j*D_ + f0 + tx];
    }
    __syncthreads();
    #pragma unroll
    for (int r=0;r<4;r++){
        int f = f0 + ty + r*8;
        float v = ts[tx][ty + r*8];
        size_t o = ((size_t)(h*D_ + f))*N_ + j0 + tx;
        g_whT_hi[o] = __float2half_rn(v);
    }
}

// ---------------- K2: src/dst dots -> per-node exp factors ---------------
__global__ void srcdst_k(const float* __restrict__ avec) {
    int h = blockIdx.y;
    int warp = threadIdx.x >> 5, lane = threadIdx.x & 31;
    int i = blockIdx.x*8 + warp;
    const float* wh = g_Wh + ((size_t)h*N_ + i)*D_;
    const float* av = avec + h*2*D_;
    float4 w4 = *(const float4*)&wh[lane*4];
    float4 s4 = *(const float4*)&av[lane*4];
    float4 d4 = *(const float4*)&av[D_ + lane*4];
    float s = w4.x*s4.x + w4.y*s4.y + w4.z*s4.z + w4.w*s4.w;
    float d = w4.x*d4.x + w4.y*d4.y + w4.z*d4.z + w4.w*d4.w;
    #pragma unroll
    for (int o=16;o>0;o>>=1){
        s += __shfl_down_sync(0xffffffffu, s, o);
        d += __shfl_down_sync(0xffffffffu, d, o);
    }
    if (lane==0){
        g_EFs[h*N_+i] = make_float2(fexp(s), fexp(ALPHA_*s));
        g_EFd[h*N_+i] = make_float2(fexp(d), fexp(ALPHA_*d));
    }
}

// ---------------- K3: warp-specialized attn, fp16 single-term -------------
// P fp16 tile; W fp16 tile. 1 MMA per (mt,nt,kt).
#define PB    0
#define WB    16384
#define BUFSZ 32768
#define OFF_L (2*BUFSZ)
#define SMEM_DYN (2*BUFSZ + 512 + 1024)

__global__ __launch_bounds__(512,1) void attn_hmma(float* __restrict__ out_ext, int stage) {
    extern __shared__ char dsm[];
    uint32_t raw = smem_u32(dsm);
    uint32_t sb  = (raw + 1023) & ~1023u;
    char* bp = dsm + (sb - raw);
    float* sml = (float*)(bp + OFF_L);

    int h = blockIdx.y, i0 = blockIdx.x*128;
    int tid = threadIdx.x, lane = tid & 31, wid = tid >> 5;
    bool producer = (wid >= 8);

    if (producer) {
        int ptid = tid - 256;
        int r = ptid >> 1, jh = ptid & 1;
        float2 efs = g_EFs[h*N_ + i0 + r];
        float Ei = efs.x, Fi = efs.y;
        const float2*   efd    = g_EFd + h*N_;
        const unsigned* adjrow = g_adjb + (size_t)(i0+r)*NW_;
        const char* whh = (const char*)(g_whT_hi + (size_t)h*D_*N_);
        float rsum = 0.f;

        auto loadW = [&](uint32_t tb, int c){
            int j0 = c * 64;
            #pragma unroll
            for (int l=0;l<4;l++){
                int idx = ptid + l*256;
                int f = idx >> 3, seg = idx & 7;
                size_t go = (((size_t)f*N_ + j0) << 1) + (size_t)seg*16;
                uint32_t so = SW128((uint32_t)(f*128 + seg*16));
                cpasync16(sb + tb + WB + so, whh + go);
            }
            CP_COMMIT();
        };
        auto genP = [&](uint32_t tb, int c){
            int j0 = c * 64;
            unsigned w = adjrow[(j0>>5) + jh];
            const float4* efp = (const float4*)(efd + j0 + jh*32);
            uint32_t rb = (uint32_t)(r*128 + jh*64);
            #pragma unroll
            for (int q=0;q<16;q++){
                float4 e01 = efp[q];
                float p0 = fmaxf(Ei*e01.x, Fi*e01.y);
                float p1 = fmaxf(Ei*e01.z, Fi*e01.w);
                p0 = ((w>>(2*q  ))&1u) ? p0 : 0.f;
                p1 = ((w>>(2*q+1))&1u) ? p1 : 0.f;
                rsum += p0 + p1;
                __half2 hp = __floats2half2_rn(p0, p1);
                *(uint32_t*)(bp + tb + PB + SW128(rb + q*4)) = *(uint32_t*)&hp;
            }
        };

        loadW(0u, 0);
        genP(0u, 0);
        CP_WAIT0();
        __syncthreads();
        for (int c = 0; c < 64; ++c) {
            uint32_t nb = (uint32_t)(~c & 1) * BUFSZ;
            if (c < 63){
                loadW(nb, c+1);          // async first, hidden under genP
                genP(nb, c+1);
                CP_WAIT0();
            }
            __syncthreads();
        }
        float full = rsum + __shfl_xor_sync(0xffffffffu, rsum, 1);
        if (!(ptid & 1)) sml[r] = 1.0f / full;
        __syncthreads();
    } else {
        int wm = wid >> 2, wn = wid & 3;
        float acc[4][4][4];
        #pragma unroll
        for (int a=0;a<4;a++)
            #pragma unroll
            for (int b=0;b<4;b++)
                #pragma unroll
                for (int c=0;c<4;c++) acc[a][b][c]=0.f;

        __syncthreads();
        for (int c = 0; c < 64; ++c) {
            uint32_t tb = (uint32_t)(c & 1) * BUFSZ;
            #pragma unroll
            for (int kt=0;kt<4;kt++){
                uint32_t kb = (uint32_t)(kt*32 + (lane>>4)*16);
                uint32_t bh[4][2];
                #pragma unroll
                for (int pp=0;pp<2;pp++){
                    uint32_t off = SW128((uint32_t)((wn*32 + pp*16 + (lane&15))*128) + kb);
                    uint32_t t0[4];
                    ldsm4(t0, sb + tb + WB + off);
                    bh[pp*2  ][0]=t0[0]; bh[pp*2  ][1]=t0[2];
                    bh[pp*2+1][0]=t0[1]; bh[pp*2+1][1]=t0[3];
                }
                #pragma unroll
                for (int mt=0;mt<4;mt++){
                    uint32_t off = SW128((uint32_t)((wm*64 + mt*16 + (lane&15))*128) + kb);
                    uint32_t ah[4];
                    ldsm4(ah, sb + tb + PB + off);
                    #pragma unroll
                    for (int nt=0;nt<4;nt++)
                        mma16816h(acc[mt][nt], ah, bh[nt]);
                }
            }
            __syncthreads();
        }
        __syncthreads();                 // sml ready
        #pragma unroll
        for (int mt=0;mt<4;mt++){
            int r0 = wm*64 + mt*16 + (lane>>2);
            float il0 = sml[r0], il1 = sml[r0+8];
            #pragma unroll
            for (int nt=0;nt<4;nt++){
                int fcol = wn*32 + nt*8 + (lane&3)*2;
                float2 v0, v1;
                v0.x = eluf(acc[mt][nt][0]*il0);
                v0.y = eluf(acc[mt][nt][1]*il0);
                v1.x = eluf(acc[mt][nt][2]*il1);
                v1.y = eluf(acc[mt][nt][3]*il1);
                if (stage == 1){
                    size_t o0 = ((size_t)(i0+r0  )*KX_ + h*D_ + fcol);
                    size_t o1 = ((size_t)(i0+r0+8)*KX_ + h*D_ + fcol);
                    float l0a, l0b, l1a, l1b;
                    uint32_t h0 = pack_hi(v0.x, v0.y, l0a, l0b);
                    uint32_t h1 = pack_hi(v1.x, v1.y, l1a, l1b);
                    __nv_bfloat162 lo0 = __floats2bfloat162_rn(l0a, l0b);
                    __nv_bfloat162 lo1 = __floats2bfloat162_rn(l1a, l1b);
                    *(uint32_t*)((char*)g_x_hi + o0*2) = h0;
                    *(uint32_t*)((char*)g_x_lo + o0*2) = *(uint32_t*)&lo0;
                    *(uint32_t*)((char*)g_x_hi + o1*2) = h1;
                    *(uint32_t*)((char*)g_x_lo + o1*2) = *(uint32_t*)&lo1;
                } else {
                    *(float2*)(out_ext + (size_t)(i0+r0  )*KX_ + h*D_ + fcol) = v0;
                    *(float2*)(out_ext + (size_t)(i0+r0+8)*KX_ + h*D_ + fcol) = v1;
                }
            }
        }
    }
}

// ---------------- launch ----------------
extern "C" void kernel_launch(void* const* d_in, const int* in_sizes, int n_in,
                              void* d_out, int out_size) {
    const float* chems = (const float*)d_in[0];
    const int*   adj   = (const int*)  d_in[1];
    const float* W1    = (const float*)d_in[2];
    const float* a1    = (const float*)d_in[3];
    const float* W2    = (const float*)d_in[4];
    const float* a2    = (const float*)d_in[5];
    float* out = (float*)d_out;

    cudaFuncSetAttribute(attn_hmma, cudaFuncAttributeMaxDynamicSharedMemorySize, SMEM_DYN);
    cudaFuncSetAttribute(gemm_hmma, cudaFuncAttributeMaxDynamicSharedMemorySize, SMEMG);

    pack_adj<<<1024, 256>>>(adj);
    split_ch<<<H_*N_*D_/1024, 256>>>(chems);
    split_WT<<<dim3(4, 4, H_), 256>>>(W1, 128, 1);
    split_WT<<<dim3(16, 4, H_), 256>>>(W2, 512, 2);

    // stage 1
    gemm_hmma<<<dim3(N_/128, H_), 256, SMEMG>>>(1, 128);
    cvt_whT<<<dim3(N_/32, D_/32, H_), 256>>>();
    srcdst_k<<<dim3(N_/8, H_), 256>>>(a1);
    attn_hmma<<<dim3(N_/128, H_), 512, SMEM_DYN>>>(nullptr, 1);

    // stage 2
    gemm_hmma<<<dim3(N_/128, H_), 256, SMEMG>>>(2, 512);
    cvt_whT<<<dim3(N_/32, D_/32, H_), 256>>>();
    srcdst_k<<<dim3(N_/8, H_), 256>>>(a2);
    attn_hmma<<<dim3(N_/128, H_), 512, SMEM_DYN>>>(out, 2);
}